// round 1
// baseline (speedup 1.0000x reference)
#include <cuda_runtime.h>
#include <math.h>

#define L    3136
#define HW   56
#define DM   96
#define DI   192
#define NS   16
#define KDIR 4
#define RR   6
#define NC   49
#define LC   64

// ---------------- scratch (device globals; no allocation) ----------------
__device__ float g_xc[DI * L];          // conv input, channel-major [d][s]
__device__ float g_z[L * DI];           // gate, pixel-major [s][d]
__device__ float g_xconv[DI * L];       // conv output, channel-major [d][s]
__device__ float g_dts[KDIR * RR * L];  // low-rank dt, scan order [k*6+r][l]
__device__ float g_Bs[KDIR * L * NS];   // scan order [(k*L+l)*16+n]
__device__ float g_Cs[KDIR * L * NS];
__device__ float g_delta[KDIR * DI * L];// scan order [kd][l]
__device__ float g_P[KDIR * DI * NC * NS];   // per-chunk prod(dA)
__device__ float g_Hc[KDIR * DI * NC * NS];  // per-chunk h_end -> h_in
__device__ float g_y4[KDIR * DI * L];   // per-direction y at SPATIAL index

__device__ __forceinline__ float siluf(float x) { return x / (1.f + __expf(-x)); }
__device__ __forceinline__ float softplusf(float x) { return x > 20.f ? x : log1pf(__expf(x)); }

// ---------------- K1: in_proj GEMM (L x 96) @ (96 x 384), split xc/z ------
__global__ void k_inproj(const float* __restrict__ x, const float* __restrict__ w) {
    __shared__ float As[32 * 96];
    __shared__ float Bs[96 * 65];
    __shared__ float Csh[64 * 33];
    const int l0 = blockIdx.x * 32;
    const int o0 = blockIdx.y * 64;
    const int tid = threadIdx.x;

    for (int e = tid; e < 32 * 96; e += 256)
        As[e] = x[(l0 + e / 96) * 96 + (e % 96)];
    for (int e = tid; e < 96 * 64; e += 256) {
        int o = e / 96, c = e % 96;
        Bs[c * 65 + o] = w[(o0 + o) * 96 + c];
    }
    __syncthreads();

    const int tl = tid >> 5, to = tid & 31;
    float acc[4][2] = {};
    #pragma unroll 8
    for (int kk = 0; kk < 96; kk++) {
        float b0 = Bs[kk * 65 + to];
        float b1 = Bs[kk * 65 + to + 32];
        #pragma unroll
        for (int i = 0; i < 4; i++) {
            float a = As[(tl * 4 + i) * 96 + kk];
            acc[i][0] += a * b0;
            acc[i][1] += a * b1;
        }
    }
    __syncthreads();
    #pragma unroll
    for (int i = 0; i < 4; i++) {
        Csh[to * 33 + tl * 4 + i] = acc[i][0];
        Csh[(to + 32) * 33 + tl * 4 + i] = acc[i][1];
    }
    __syncthreads();

    // xc part: channel-major, coalesced along l
    for (int e = tid; e < 2048; e += 256) {
        int ol = e >> 5, l = e & 31;
        int o = o0 + ol;
        if (o < DI) g_xc[o * L + l0 + l] = Csh[ol * 33 + l];
    }
    // z part: pixel-major, coalesced along o, with silu
    for (int e = tid; e < 2048; e += 256) {
        int l = e >> 6, ol = e & 63;
        int o = o0 + ol;
        if (o >= DI) {
            float v = Csh[ol * 33 + l];
            g_z[(l0 + l) * DI + (o - DI)] = siluf(v);
        }
    }
}

// ---------------- K2: depthwise 3x3 conv SAME + silu ----------------------
__global__ void k_conv(const float* __restrict__ cw, const float* __restrict__ cb) {
    const int d = blockIdx.x;
    const int h = blockIdx.y * 4 + threadIdx.y;
    const int w = threadIdx.x;
    float wgt[9];
    #pragma unroll
    for (int i = 0; i < 9; i++) wgt[i] = cw[d * 9 + i];
    float acc = cb[d];
    const float* base = g_xc + d * L;
    #pragma unroll
    for (int i = 0; i < 3; i++) {
        int hh = h + i - 1;
        if (hh < 0 || hh >= HW) continue;
        #pragma unroll
        for (int j = 0; j < 3; j++) {
            int ww = w + j - 1;
            if (ww < 0 || ww >= HW) continue;
            acc += base[hh * HW + ww] * wgt[i * 3 + j];
        }
    }
    g_xconv[d * L + h * HW + w] = siluf(acc);
}

// ---------------- K3a: x_dbl projection, scatter into scan order ----------
__global__ void k_xdbl(const float* __restrict__ xpw) {
    __shared__ float xv[DI];
    const int s = blockIdx.x;
    const int tid = threadIdx.x;  // 192 threads
    xv[tid] = g_xconv[tid * L + s];
    __syncthreads();
    if (tid < KDIR * 38) {
        int k = tid / 38, r = tid % 38;
        const float* wrow = xpw + (k * 38 + r) * DI;
        float acc = 0.f;
        #pragma unroll 8
        for (int d = 0; d < DI; d++) acc += xv[d] * wrow[d];
        int hs = s / HW, ws = s % HW;
        int tpos = ws * HW + hs;
        int lp = (k == 0) ? s : (k == 1) ? tpos : (k == 2) ? (L - 1 - s) : (L - 1 - tpos);
        if (r < RR)            g_dts[(k * RR + r) * L + lp] = acc;
        else if (r < RR + NS)  g_Bs[(k * L + lp) * NS + (r - RR)] = acc;
        else                   g_Cs[(k * L + lp) * NS + (r - RR - NS)] = acc;
    }
}

// ---------------- K3b: dt projection + softplus -> delta (scan order) -----
__global__ void k_delta(const float* __restrict__ dtw, const float* __restrict__ dtb) {
    const int kd = blockIdx.x;   // 0..767
    const int k = kd / DI;
    float wr[6];
    #pragma unroll
    for (int r = 0; r < 6; r++) wr[r] = dtw[kd * 6 + r];
    const float b = dtb[kd];
    for (int l = threadIdx.x; l < L; l += blockDim.x) {
        float acc = b;
        #pragma unroll
        for (int r = 0; r < 6; r++) acc += g_dts[(k * RR + r) * L + l] * wr[r];
        g_delta[kd * L + l] = softplusf(acc);
    }
}

// ---------------- K4a: chunk scan pass A (prod dA, h_end) -----------------
__global__ void k_scanA(const float* __restrict__ alogs) {
    const int gid = blockIdx.x * 16 + (threadIdx.x >> 4);
    const int n = threadIdx.x & 15;
    const int kd = gid / NC, c = gid % NC;
    const int k = kd / DI, d = kd % DI;
    const float a = -__expf(alogs[kd * NS + n]);
    float P = 1.f, h = 0.f;
    const float* dptr = g_delta + kd * L;
    const float* bptr = g_Bs + k * L * NS;
    const float* xptr = g_xconv + d * L;
    int l = c * LC;
    int q56 = l / HW, r56 = l % HW;
    #pragma unroll 4
    for (int i = 0; i < LC; i++) {
        int s1 = r56 * HW + q56;
        int s = (k == 0) ? l : (k == 1) ? s1 : (k == 2) ? (L - 1 - l) : (L - 1 - s1);
        float delta = dptr[l];
        float Bv = bptr[l * NS + n];
        float xvv = xptr[s];
        float dA = __expf(delta * a);
        h = dA * h + delta * Bv * xvv;
        P *= dA;
        l++; r56++;
        if (r56 == HW) { r56 = 0; q56++; }
    }
    int idx = (kd * NC + c) * NS + n;
    g_P[idx] = P;
    g_Hc[idx] = h;
}

// ---------------- K4b: carry scan across chunks (49 steps) ----------------
__global__ void k_scanB() {
    const int t = blockIdx.x * blockDim.x + threadIdx.x;  // 12288 threads
    const int kd = t >> 4, n = t & 15;
    float carry = 0.f;
    const int base = kd * NC * NS + n;
    for (int c = 0; c < NC; c++) {
        int idx = base + c * NS;
        float p = g_P[idx];
        float he = g_Hc[idx];
        g_Hc[idx] = carry;    // h_in for chunk c
        carry = p * carry + he;
    }
}

// ---------------- K4c: chunk scan pass C, emit y at spatial index ---------
__global__ void k_scanC(const float* __restrict__ alogs, const float* __restrict__ ds) {
    const int gid = blockIdx.x * 16 + (threadIdx.x >> 4);
    const int n = threadIdx.x & 15;
    const int kd = gid / NC, c = gid % NC;
    const int k = kd / DI, d = kd % DI;
    const float a = -__expf(alogs[kd * NS + n]);
    const float Dv = ds[kd];
    float h = g_Hc[(kd * NC + c) * NS + n];
    const float* dptr = g_delta + kd * L;
    const float* bptr = g_Bs + k * L * NS;
    const float* cptr = g_Cs + k * L * NS;
    const float* xptr = g_xconv + d * L;
    float* yptr = g_y4 + kd * L;
    int l = c * LC;
    int q56 = l / HW, r56 = l % HW;
    #pragma unroll 4
    for (int i = 0; i < LC; i++) {
        int s1 = r56 * HW + q56;
        int s = (k == 0) ? l : (k == 1) ? s1 : (k == 2) ? (L - 1 - l) : (L - 1 - s1);
        float delta = dptr[l];
        float Bv = bptr[l * NS + n];
        float Cv = cptr[l * NS + n];
        float xvv = xptr[s];
        float dA = __expf(delta * a);
        h = dA * h + delta * Bv * xvv;
        float v = h * Cv;
        v += __shfl_xor_sync(0xffffffffu, v, 1);
        v += __shfl_xor_sync(0xffffffffu, v, 2);
        v += __shfl_xor_sync(0xffffffffu, v, 4);
        v += __shfl_xor_sync(0xffffffffu, v, 8);
        if (n == 0) yptr[s] = v + Dv * xvv;
        l++; r56++;
        if (r56 == HW) { r56 = 0; q56++; }
    }
}

// ---------------- K5: merge 4 dirs + LayerNorm + z-gate + out_proj --------
__global__ void k_merge_out(const float* __restrict__ lnw, const float* __restrict__ lnb,
                            const float* __restrict__ ow, float* __restrict__ out) {
    __shared__ float yt[DI * 33];
    __shared__ float red1[256], red2[256];
    __shared__ float mu_s[32], rs_s[32];
    const int s0 = blockIdx.x * 32;
    const int tid = threadIdx.x;

    for (int e = tid; e < DI * 32; e += 256) {
        int d = e >> 5, ls = e & 31;
        int s = s0 + ls;
        float v = g_y4[d * L + s] + g_y4[(DI + d) * L + s] +
                  g_y4[(2 * DI + d) * L + s] + g_y4[(3 * DI + d) * L + s];
        yt[d * 33 + ls] = v;
    }
    __syncthreads();
    {
        int j = tid >> 5, ls = tid & 31;
        float s1 = 0.f, s2 = 0.f;
        for (int d = j; d < DI; d += 8) {
            float v = yt[d * 33 + ls];
            s1 += v; s2 += v * v;
        }
        red1[tid] = s1; red2[tid] = s2;
    }
    __syncthreads();
    if (tid < 32) {
        float s1 = 0.f, s2 = 0.f;
        #pragma unroll
        for (int j = 0; j < 8; j++) { s1 += red1[j * 32 + tid]; s2 += red2[j * 32 + tid]; }
        float mu = s1 / DI;
        float var = s2 / DI - mu * mu;
        mu_s[tid] = mu;
        rs_s[tid] = rsqrtf(var + 1e-5f);
    }
    __syncthreads();
    for (int e = tid; e < DI * 32; e += 256) {
        int ls = e / DI, d = e % DI;
        float v = yt[d * 33 + ls];
        v = (v - mu_s[ls]) * rs_s[ls] * lnw[d] + lnb[d];
        v *= g_z[(s0 + ls) * DI + d];
        yt[d * 33 + ls] = v;
    }
    __syncthreads();
    {
        int ls = tid & 31, og = tid >> 5;
        float acc[12] = {};
        for (int d = 0; d < DI; d++) {
            float yv = yt[d * 33 + ls];
            #pragma unroll
            for (int j = 0; j < 12; j++) acc[j] += yv * ow[(og + 8 * j) * DI + d];
        }
        #pragma unroll
        for (int j = 0; j < 12; j++) out[(s0 + ls) * DM + og + 8 * j] = acc[j];
    }
}

// ---------------- launch ---------------------------------------------------
extern "C" void kernel_launch(void* const* d_in, const int* in_sizes, int n_in,
                              void* d_out, int out_size) {
    const float* x     = (const float*)d_in[0];
    const float* inw   = (const float*)d_in[1];
    const float* cw    = (const float*)d_in[2];
    const float* cb    = (const float*)d_in[3];
    const float* xpw   = (const float*)d_in[4];
    const float* dtw   = (const float*)d_in[5];
    const float* dtb   = (const float*)d_in[6];
    const float* alogs = (const float*)d_in[7];
    const float* ds    = (const float*)d_in[8];
    const float* lnw   = (const float*)d_in[9];
    const float* lnb   = (const float*)d_in[10];
    const float* ow    = (const float*)d_in[11];
    float* out = (float*)d_out;

    k_inproj<<<dim3(98, 6), 256>>>(x, inw);
    k_conv<<<dim3(192, 14), dim3(56, 4)>>>(cw, cb);
    k_xdbl<<<3136, 192>>>(xpw);
    k_delta<<<768, 256>>>(dtw, dtb);
    k_scanA<<<2352, 256>>>(alogs);
    k_scanB<<<48, 256>>>();
    k_scanC<<<2352, 256>>>(alogs, ds);
    k_merge_out<<<98, 256>>>(lnw, lnb, ow, out);
}

// round 2
// speedup vs baseline: 3.6319x; 3.6319x over previous
#include <cuda_runtime.h>
#include <math.h>

#define L    3136
#define HW   56
#define DM   96
#define DI   192
#define NS   16
#define KDIR 4
#define RR   6
#define NC   49
#define LC   64

// ---------------- scratch (device globals; no allocation) ----------------
__device__ float g_xc[DI * L];          // conv input, channel-major [d][s]
__device__ float g_z[L * DI];           // gate, pixel-major [s][d]
__device__ float g_xconv[DI * L];       // conv output, channel-major [d][s]
__device__ float g_dts[KDIR * RR * L];  // low-rank dt, scan order [k*6+r][l]
__device__ float g_Bs[KDIR * L * NS];   // scan order [(k*L+l)*16+n]
__device__ float g_Cs[KDIR * L * NS];
__device__ float g_delta[KDIR * DI * L];// scan order [kd][l]
__device__ float g_P[KDIR * DI * NC * NS];   // per-chunk prod(dA)
__device__ float g_Hc[KDIR * DI * NC * NS];  // per-chunk h_end -> h_in
__device__ float g_y4[KDIR * DI * L];   // per-direction y at SPATIAL index

__device__ __forceinline__ float siluf(float x) { return x / (1.f + __expf(-x)); }
__device__ __forceinline__ float softplusf(float x) { return x > 20.f ? x : log1pf(__expf(x)); }

// ---------------- K1: in_proj GEMM (L x 96) @ (96 x 384), split xc/z ------
__global__ void k_inproj(const float* __restrict__ x, const float* __restrict__ w) {
    __shared__ float As[32 * 96];
    __shared__ float Bs[96 * 65];
    __shared__ float Csh[64 * 33];
    const int l0 = blockIdx.x * 32;
    const int o0 = blockIdx.y * 64;
    const int tid = threadIdx.x;

    for (int e = tid; e < 32 * 96; e += 256)
        As[e] = x[(l0 + e / 96) * 96 + (e % 96)];
    for (int e = tid; e < 96 * 64; e += 256) {
        int o = e / 96, c = e % 96;
        Bs[c * 65 + o] = w[(o0 + o) * 96 + c];
    }
    __syncthreads();

    const int tl = tid >> 5, to = tid & 31;
    float acc[4][2] = {};
    #pragma unroll 8
    for (int kk = 0; kk < 96; kk++) {
        float b0 = Bs[kk * 65 + to];
        float b1 = Bs[kk * 65 + to + 32];
        #pragma unroll
        for (int i = 0; i < 4; i++) {
            float a = As[(tl * 4 + i) * 96 + kk];
            acc[i][0] += a * b0;
            acc[i][1] += a * b1;
        }
    }
    __syncthreads();
    #pragma unroll
    for (int i = 0; i < 4; i++) {
        Csh[to * 33 + tl * 4 + i] = acc[i][0];
        Csh[(to + 32) * 33 + tl * 4 + i] = acc[i][1];
    }
    __syncthreads();

    // xc part: channel-major, coalesced along l
    for (int e = tid; e < 2048; e += 256) {
        int ol = e >> 5, l = e & 31;
        int o = o0 + ol;
        if (o < DI) g_xc[o * L + l0 + l] = Csh[ol * 33 + l];
    }
    // z part: pixel-major, coalesced along o, with silu
    for (int e = tid; e < 2048; e += 256) {
        int l = e >> 6, ol = e & 63;
        int o = o0 + ol;
        if (o >= DI) {
            float v = Csh[ol * 33 + l];
            g_z[(l0 + l) * DI + (o - DI)] = siluf(v);
        }
    }
}

// ---------------- K2: depthwise 3x3 conv SAME + silu ----------------------
__global__ void k_conv(const float* __restrict__ cw, const float* __restrict__ cb) {
    const int d = blockIdx.x;
    const int h = blockIdx.y * 4 + threadIdx.y;
    const int w = threadIdx.x;
    float wgt[9];
    #pragma unroll
    for (int i = 0; i < 9; i++) wgt[i] = cw[d * 9 + i];
    float acc = cb[d];
    const float* base = g_xc + d * L;
    #pragma unroll
    for (int i = 0; i < 3; i++) {
        int hh = h + i - 1;
        if (hh < 0 || hh >= HW) continue;
        #pragma unroll
        for (int j = 0; j < 3; j++) {
            int ww = w + j - 1;
            if (ww < 0 || ww >= HW) continue;
            acc += base[hh * HW + ww] * wgt[i * 3 + j];
        }
    }
    g_xconv[d * L + h * HW + w] = siluf(acc);
}

// ---------------- K3a: x_dbl projection GEMM, scatter into scan order -----
// out[row, s] = sum_d xconv[d, s] * xpw[row*192 + d],  row = k*38 + r (152 rows)
// Block: 64 pixels, 256 threads (8 warps). Each thread: 20 rows x 2 pixels.
#define XD_KD 48
__global__ void k_xdbl(const float* __restrict__ xpw) {
    __shared__ float xs[XD_KD * 64];    // [dd][ss]
    __shared__ float ws[160 * XD_KD];   // [row][dd], rows 152..159 zero
    const int s0 = blockIdx.x * 64;
    const int tid = threadIdx.x;
    const int tx = tid & 31;
    const int r0 = (tid >> 5) * 20;     // 8 warps * 20 rows = 160

    float acc[20][2];
    #pragma unroll
    for (int j = 0; j < 20; j++) { acc[j][0] = 0.f; acc[j][1] = 0.f; }

    for (int d0 = 0; d0 < DI; d0 += XD_KD) {
        __syncthreads();
        #pragma unroll
        for (int e = tid; e < XD_KD * 64; e += 256) {
            int dd = e >> 6, ss = e & 63;
            xs[e] = g_xconv[(d0 + dd) * L + s0 + ss];
        }
        for (int e = tid; e < 160 * XD_KD; e += 256) {
            int row = e / XD_KD, dd = e % XD_KD;
            ws[e] = (row < 152) ? xpw[row * DI + d0 + dd] : 0.f;
        }
        __syncthreads();
        #pragma unroll 4
        for (int dd = 0; dd < XD_KD; dd++) {
            float xv0 = xs[dd * 64 + tx];
            float xv1 = xs[dd * 64 + tx + 32];
            #pragma unroll
            for (int j = 0; j < 20; j++) {
                float wv = ws[(r0 + j) * XD_KD + dd];
                acc[j][0] += wv * xv0;
                acc[j][1] += wv * xv1;
            }
        }
    }

    // scatter with direction permutation
    #pragma unroll
    for (int j = 0; j < 20; j++) {
        int row = r0 + j;
        if (row >= 152) break;
        int k = row / 38, r = row % 38;
        #pragma unroll
        for (int c = 0; c < 2; c++) {
            int s = s0 + tx + 32 * c;
            int hs = s / HW, wsp = s % HW;
            int tpos = wsp * HW + hs;
            int lp = (k == 0) ? s : (k == 1) ? tpos : (k == 2) ? (L - 1 - s) : (L - 1 - tpos);
            float v = acc[j][c];
            if (r < RR)            g_dts[(k * RR + r) * L + lp] = v;
            else if (r < RR + NS)  g_Bs[(k * L + lp) * NS + (r - RR)] = v;
            else                   g_Cs[(k * L + lp) * NS + (r - RR - NS)] = v;
        }
    }
}

// ---------------- K3b: dt projection + softplus -> delta (scan order) -----
__global__ void k_delta(const float* __restrict__ dtw, const float* __restrict__ dtb) {
    const int kd = blockIdx.x;   // 0..767
    const int k = kd / DI;
    float wr[6];
    #pragma unroll
    for (int r = 0; r < 6; r++) wr[r] = dtw[kd * 6 + r];
    const float b = dtb[kd];
    for (int l = threadIdx.x; l < L; l += blockDim.x) {
        float acc = b;
        #pragma unroll
        for (int r = 0; r < 6; r++) acc += g_dts[(k * RR + r) * L + l] * wr[r];
        g_delta[kd * L + l] = softplusf(acc);
    }
}

// ---------------- K4a: chunk scan pass A (prod dA, h_end) -----------------
__global__ void k_scanA(const float* __restrict__ alogs) {
    const int gid = blockIdx.x * 16 + (threadIdx.x >> 4);
    const int n = threadIdx.x & 15;
    const int kd = gid / NC, c = gid % NC;
    const int k = kd / DI, d = kd % DI;
    const float a = -__expf(alogs[kd * NS + n]);
    float P = 1.f, h = 0.f;
    const float* dptr = g_delta + kd * L;
    const float* bptr = g_Bs + k * L * NS;
    const float* xptr = g_xconv + d * L;
    int l = c * LC;
    int q56 = l / HW, r56 = l % HW;
    #pragma unroll 4
    for (int i = 0; i < LC; i++) {
        int s1 = r56 * HW + q56;
        int s = (k == 0) ? l : (k == 1) ? s1 : (k == 2) ? (L - 1 - l) : (L - 1 - s1);
        float delta = dptr[l];
        float Bv = bptr[l * NS + n];
        float xvv = xptr[s];
        float dA = __expf(delta * a);
        h = dA * h + delta * Bv * xvv;
        P *= dA;
        l++; r56++;
        if (r56 == HW) { r56 = 0; q56++; }
    }
    int idx = (kd * NC + c) * NS + n;
    g_P[idx] = P;
    g_Hc[idx] = h;
}

// ---------------- K4b: carry scan across chunks (49 steps) ----------------
__global__ void k_scanB() {
    const int t = blockIdx.x * blockDim.x + threadIdx.x;  // 12288 threads
    const int kd = t >> 4, n = t & 15;
    float carry = 0.f;
    const int base = kd * NC * NS + n;
    for (int c = 0; c < NC; c++) {
        int idx = base + c * NS;
        float p = g_P[idx];
        float he = g_Hc[idx];
        g_Hc[idx] = carry;    // h_in for chunk c
        carry = p * carry + he;
    }
}

// ---------------- K4c: chunk scan pass C, emit y at spatial index ---------
__global__ void k_scanC(const float* __restrict__ alogs, const float* __restrict__ ds) {
    const int gid = blockIdx.x * 16 + (threadIdx.x >> 4);
    const int n = threadIdx.x & 15;
    const int kd = gid / NC, c = gid % NC;
    const int k = kd / DI, d = kd % DI;
    const float a = -__expf(alogs[kd * NS + n]);
    const float Dv = ds[kd];
    float h = g_Hc[(kd * NC + c) * NS + n];
    const float* dptr = g_delta + kd * L;
    const float* bptr = g_Bs + k * L * NS;
    const float* cptr = g_Cs + k * L * NS;
    const float* xptr = g_xconv + d * L;
    float* yptr = g_y4 + kd * L;
    int l = c * LC;
    int q56 = l / HW, r56 = l % HW;
    #pragma unroll 4
    for (int i = 0; i < LC; i++) {
        int s1 = r56 * HW + q56;
        int s = (k == 0) ? l : (k == 1) ? s1 : (k == 2) ? (L - 1 - l) : (L - 1 - s1);
        float delta = dptr[l];
        float Bv = bptr[l * NS + n];
        float Cv = cptr[l * NS + n];
        float xvv = xptr[s];
        float dA = __expf(delta * a);
        h = dA * h + delta * Bv * xvv;
        float v = h * Cv;
        v += __shfl_xor_sync(0xffffffffu, v, 1);
        v += __shfl_xor_sync(0xffffffffu, v, 2);
        v += __shfl_xor_sync(0xffffffffu, v, 4);
        v += __shfl_xor_sync(0xffffffffu, v, 8);
        if (n == 0) yptr[s] = v + Dv * xvv;
        l++; r56++;
        if (r56 == HW) { r56 = 0; q56++; }
    }
}

// ---------------- K5: merge 4 dirs + LayerNorm + z-gate + out_proj --------
__global__ void k_merge_out(const float* __restrict__ lnw, const float* __restrict__ lnb,
                            const float* __restrict__ ow, float* __restrict__ out) {
    __shared__ float yt[DI * 33];
    __shared__ float red1[256], red2[256];
    __shared__ float mu_s[32], rs_s[32];
    const int s0 = blockIdx.x * 32;
    const int tid = threadIdx.x;

    for (int e = tid; e < DI * 32; e += 256) {
        int d = e >> 5, ls = e & 31;
        int s = s0 + ls;
        float v = g_y4[d * L + s] + g_y4[(DI + d) * L + s] +
                  g_y4[(2 * DI + d) * L + s] + g_y4[(3 * DI + d) * L + s];
        yt[d * 33 + ls] = v;
    }
    __syncthreads();
    {
        int j = tid >> 5, ls = tid & 31;
        float s1 = 0.f, s2 = 0.f;
        for (int d = j; d < DI; d += 8) {
            float v = yt[d * 33 + ls];
            s1 += v; s2 += v * v;
        }
        red1[tid] = s1; red2[tid] = s2;
    }
    __syncthreads();
    if (tid < 32) {
        float s1 = 0.f, s2 = 0.f;
        #pragma unroll
        for (int j = 0; j < 8; j++) { s1 += red1[j * 32 + tid]; s2 += red2[j * 32 + tid]; }
        float mu = s1 / DI;
        float var = s2 / DI - mu * mu;
        mu_s[tid] = mu;
        rs_s[tid] = rsqrtf(var + 1e-5f);
    }
    __syncthreads();
    for (int e = tid; e < DI * 32; e += 256) {
        int ls = e / DI, d = e % DI;
        float v = yt[d * 33 + ls];
        v = (v - mu_s[ls]) * rs_s[ls] * lnw[d] + lnb[d];
        v *= g_z[(s0 + ls) * DI + d];
        yt[d * 33 + ls] = v;
    }
    __syncthreads();
    {
        int ls = tid & 31, og = tid >> 5;
        float acc[12] = {};
        for (int d = 0; d < DI; d++) {
            float yv = yt[d * 33 + ls];
            #pragma unroll
            for (int j = 0; j < 12; j++) acc[j] += yv * ow[(og + 8 * j) * DI + d];
        }
        #pragma unroll
        for (int j = 0; j < 12; j++) out[(s0 + ls) * DM + og + 8 * j] = acc[j];
    }
}

// ---------------- launch ---------------------------------------------------
extern "C" void kernel_launch(void* const* d_in, const int* in_sizes, int n_in,
                              void* d_out, int out_size) {
    const float* x     = (const float*)d_in[0];
    const float* inw   = (const float*)d_in[1];
    const float* cw    = (const float*)d_in[2];
    const float* cb    = (const float*)d_in[3];
    const float* xpw   = (const float*)d_in[4];
    const float* dtw   = (const float*)d_in[5];
    const float* dtb   = (const float*)d_in[6];
    const float* alogs = (const float*)d_in[7];
    const float* ds    = (const float*)d_in[8];
    const float* lnw   = (const float*)d_in[9];
    const float* lnb   = (const float*)d_in[10];
    const float* ow    = (const float*)d_in[11];
    float* out = (float*)d_out;

    k_inproj<<<dim3(98, 6), 256>>>(x, inw);
    k_conv<<<dim3(192, 14), dim3(56, 4)>>>(cw, cb);
    k_xdbl<<<49, 256>>>(xpw);
    k_delta<<<768, 256>>>(dtw, dtb);
    k_scanA<<<2352, 256>>>(alogs);
    k_scanB<<<48, 256>>>();
    k_scanC<<<2352, 256>>>(alogs, ds);
    k_merge_out<<<98, 256>>>(lnw, lnb, ow, out);
}

// round 3
// speedup vs baseline: 4.2934x; 1.1821x over previous
#include <cuda_runtime.h>
#include <math.h>

#define L    3136
#define HW   56
#define DM   96
#define DI   192
#define NS   16
#define KDIR 4
#define RR   6
#define NC   49
#define LC   64

// ---------------- scratch (device globals; no allocation) ----------------
__device__ float g_xc[DI * L];          // conv input, channel-major [d][s]
__device__ float g_z[L * DI];           // gate, pixel-major [s][d]
__device__ float g_xconv[DI * L];       // conv output, channel-major [d][s]
__device__ float g_dts[KDIR * RR * L];  // low-rank dt, scan order [k*6+r][l]
__device__ float g_Bs[KDIR * L * NS];   // scan order [(k*L+l)*16+n]
__device__ float g_Cs[KDIR * L * NS];
__device__ float g_delta[KDIR * DI * L];// scan order [kd][l]
__device__ float g_P[KDIR * DI * NC * NS];   // per-chunk prod(dA)
__device__ float g_Hc[KDIR * DI * NC * NS];  // per-chunk h_end -> h_in
__device__ float g_y4[KDIR * DI * L];   // per-direction y at SPATIAL index

__device__ __forceinline__ float siluf(float x) { return x / (1.f + __expf(-x)); }
__device__ __forceinline__ float softplusf(float x) {
    return x > 20.f ? x : __logf(1.f + __expf(x));
}
__device__ __forceinline__ float ex2f(float x) {
    float r;
    asm("ex2.approx.f32 %0, %1;" : "=f"(r) : "f"(x));
    return r;
}
#define LOG2E 1.4426950408889634f

// ---------------- K1: in_proj GEMM (L x 96) @ (96 x 384), split xc/z ------
__global__ void k_inproj(const float* __restrict__ x, const float* __restrict__ w) {
    __shared__ float As[32 * 96];
    __shared__ float Bs[96 * 65];
    __shared__ float Csh[64 * 33];
    const int l0 = blockIdx.x * 32;
    const int o0 = blockIdx.y * 64;
    const int tid = threadIdx.x;

    for (int e = tid; e < 32 * 96; e += 256)
        As[e] = x[(l0 + e / 96) * 96 + (e % 96)];
    for (int e = tid; e < 96 * 64; e += 256) {
        int o = e / 96, c = e % 96;
        Bs[c * 65 + o] = w[(o0 + o) * 96 + c];
    }
    __syncthreads();

    const int tl = tid >> 5, to = tid & 31;
    float acc[4][2] = {};
    #pragma unroll 8
    for (int kk = 0; kk < 96; kk++) {
        float b0 = Bs[kk * 65 + to];
        float b1 = Bs[kk * 65 + to + 32];
        #pragma unroll
        for (int i = 0; i < 4; i++) {
            float a = As[(tl * 4 + i) * 96 + kk];
            acc[i][0] += a * b0;
            acc[i][1] += a * b1;
        }
    }
    __syncthreads();
    #pragma unroll
    for (int i = 0; i < 4; i++) {
        Csh[to * 33 + tl * 4 + i] = acc[i][0];
        Csh[(to + 32) * 33 + tl * 4 + i] = acc[i][1];
    }
    __syncthreads();

    for (int e = tid; e < 2048; e += 256) {
        int ol = e >> 5, l = e & 31;
        int o = o0 + ol;
        if (o < DI) g_xc[o * L + l0 + l] = Csh[ol * 33 + l];
    }
    for (int e = tid; e < 2048; e += 256) {
        int l = e >> 6, ol = e & 63;
        int o = o0 + ol;
        if (o >= DI) {
            float v = Csh[ol * 33 + l];
            g_z[(l0 + l) * DI + (o - DI)] = siluf(v);
        }
    }
}

// ---------------- K2: depthwise 3x3 conv SAME + silu ----------------------
__global__ void k_conv(const float* __restrict__ cw, const float* __restrict__ cb) {
    const int d = blockIdx.x;
    const int h = blockIdx.y * 4 + threadIdx.y;
    const int w = threadIdx.x;
    float wgt[9];
    #pragma unroll
    for (int i = 0; i < 9; i++) wgt[i] = cw[d * 9 + i];
    float acc = cb[d];
    const float* base = g_xc + d * L;
    #pragma unroll
    for (int i = 0; i < 3; i++) {
        int hh = h + i - 1;
        if (hh < 0 || hh >= HW) continue;
        #pragma unroll
        for (int j = 0; j < 3; j++) {
            int ww = w + j - 1;
            if (ww < 0 || ww >= HW) continue;
            acc += base[hh * HW + ww] * wgt[i * 3 + j];
        }
    }
    g_xconv[d * L + h * HW + w] = siluf(acc);
}

// ---------------- K3a: x_dbl projection GEMM, scatter into scan order -----
#define XD_KD 48
__global__ void k_xdbl(const float* __restrict__ xpw) {
    __shared__ float xs[XD_KD * 64];    // [dd][ss]
    __shared__ float ws[160 * XD_KD];   // [row][dd], rows 152..159 zero
    const int s0 = blockIdx.x * 64;
    const int tid = threadIdx.x;
    const int tx = tid & 31;
    const int r0 = (tid >> 5) * 20;

    float acc[20][2];
    #pragma unroll
    for (int j = 0; j < 20; j++) { acc[j][0] = 0.f; acc[j][1] = 0.f; }

    for (int d0 = 0; d0 < DI; d0 += XD_KD) {
        __syncthreads();
        #pragma unroll
        for (int e = tid; e < XD_KD * 64; e += 256) {
            int dd = e >> 6, ss = e & 63;
            xs[e] = g_xconv[(d0 + dd) * L + s0 + ss];
        }
        for (int e = tid; e < 160 * XD_KD; e += 256) {
            int row = e / XD_KD, dd = e % XD_KD;
            ws[e] = (row < 152) ? xpw[row * DI + d0 + dd] : 0.f;
        }
        __syncthreads();
        #pragma unroll 4
        for (int dd = 0; dd < XD_KD; dd++) {
            float xv0 = xs[dd * 64 + tx];
            float xv1 = xs[dd * 64 + tx + 32];
            #pragma unroll
            for (int j = 0; j < 20; j++) {
                float wv = ws[(r0 + j) * XD_KD + dd];
                acc[j][0] += wv * xv0;
                acc[j][1] += wv * xv1;
            }
        }
    }

    #pragma unroll
    for (int j = 0; j < 20; j++) {
        int row = r0 + j;
        if (row >= 152) break;
        int k = row / 38, r = row % 38;
        #pragma unroll
        for (int c = 0; c < 2; c++) {
            int s = s0 + tx + 32 * c;
            int hs = s / HW, wsp = s % HW;
            int tpos = wsp * HW + hs;
            int lp = (k == 0) ? s : (k == 1) ? tpos : (k == 2) ? (L - 1 - s) : (L - 1 - tpos);
            float v = acc[j][c];
            if (r < RR)            g_dts[(k * RR + r) * L + lp] = v;
            else if (r < RR + NS)  g_Bs[(k * L + lp) * NS + (r - RR)] = v;
            else                   g_Cs[(k * L + lp) * NS + (r - RR - NS)] = v;
        }
    }
}

// ---------------- K3b: dt projection + softplus -> delta (scan order) -----
__global__ void k_delta(const float* __restrict__ dtw, const float* __restrict__ dtb) {
    const int kd = blockIdx.x;   // 0..767
    const int k = kd / DI;
    float wr[6];
    #pragma unroll
    for (int r = 0; r < 6; r++) wr[r] = dtw[kd * 6 + r];
    const float b = dtb[kd];
    const float* dbase = g_dts + k * RR * L;
    float* obase = g_delta + kd * L;
    #pragma unroll 4
    for (int l = threadIdx.x; l < L; l += 256) {
        float acc = b;
        #pragma unroll
        for (int r = 0; r < 6; r++) acc += dbase[r * L + l] * wr[r];
        obase[l] = softplusf(acc);
    }
}

// ---------------- scan direction advance helpers ---------------------------
// scan position l -> spatial index s:
//  K=0: s=l   K=1: s=(l%56)*56+l/56   K=2: s=L-1-l   K=3: s=L-1-((l%56)*56+l/56)

template<int K>
__device__ __forceinline__ void scanA_body(int kd, int d, int c, int n,
                                           const float* __restrict__ alogs) {
    const float a2 = -__expf(alogs[kd * NS + n]) * LOG2E;
    const float* __restrict__ dptr = g_delta + kd * L;
    const float* __restrict__ bptr = g_Bs + K * L * NS;
    const float* __restrict__ xptr = g_xconv + d * L;
    int l = c * LC;
    int r56 = l % HW;
    int s;
    if (K == 0) s = l;
    else if (K == 1) s = r56 * HW + l / HW;
    else if (K == 2) s = L - 1 - l;
    else s = L - 1 - (r56 * HW + l / HW);

    float h = 0.f, sd = 0.f;
    int bofs = l * NS + n;
    #pragma unroll 4
    for (int i = 0; i < LC; i++) {
        float delta = dptr[l];
        float Bv = bptr[bofs];
        float xv = xptr[s];
        float dA = ex2f(delta * a2);
        h = fmaf(dA, h, delta * xv * Bv);
        sd += delta;
        l++; bofs += NS;
        if (K == 0) s++;
        else if (K == 2) s--;
        else if (K == 1) { r56++; s += HW; if (r56 == HW) { r56 = 0; s -= L - 1; } }
        else             { r56++; s -= HW; if (r56 == HW) { r56 = 0; s += L - 1; } }
    }
    int idx = (kd * NC + c) * NS + n;
    g_P[idx] = ex2f(a2 * sd);
    g_Hc[idx] = h;
}

__global__ void k_scanA(const float* __restrict__ alogs) {
    const int k = blockIdx.x / 588;         // 588 blocks per direction
    const int bid = blockIdx.x % 588;
    const int gl = bid * 16 + (threadIdx.x >> 4);  // group within direction
    const int n = threadIdx.x & 15;
    const int d = gl / NC, c = gl % NC;
    const int kd = k * DI + d;
    switch (k) {
        case 0: scanA_body<0>(kd, d, c, n, alogs); break;
        case 1: scanA_body<1>(kd, d, c, n, alogs); break;
        case 2: scanA_body<2>(kd, d, c, n, alogs); break;
        default: scanA_body<3>(kd, d, c, n, alogs); break;
    }
}

// ---------------- K4b: carry scan across chunks (49 steps) ----------------
__global__ void k_scanB() {
    const int t = blockIdx.x * blockDim.x + threadIdx.x;  // 12288 threads
    const int kd = t >> 4, n = t & 15;
    float carry = 0.f;
    const int base = kd * NC * NS + n;
    for (int c = 0; c < NC; c++) {
        int idx = base + c * NS;
        float p = g_P[idx];
        float he = g_Hc[idx];
        g_Hc[idx] = carry;    // h_in for chunk c
        carry = fmaf(p, carry, he);
    }
}

// ---------------- K4c: chunk scan pass C, emit y at spatial index ---------
template<int K>
__device__ __forceinline__ void scanC_body(int kd, int d, int c, int n,
                                           const float* __restrict__ alogs,
                                           const float* __restrict__ ds) {
    const float a2 = -__expf(alogs[kd * NS + n]) * LOG2E;
    const float Dv = ds[kd];
    float h = g_Hc[(kd * NC + c) * NS + n];
    const float* __restrict__ dptr = g_delta + kd * L;
    const float* __restrict__ bptr = g_Bs + K * L * NS;
    const float* __restrict__ cptr = g_Cs + K * L * NS;
    const float* __restrict__ xptr = g_xconv + d * L;
    float* __restrict__ yptr = g_y4 + kd * L;
    int l = c * LC;
    int r56 = l % HW;
    int s;
    if (K == 0) s = l;
    else if (K == 1) s = r56 * HW + l / HW;
    else if (K == 2) s = L - 1 - l;
    else s = L - 1 - (r56 * HW + l / HW);

    int bofs = l * NS + n;
    #pragma unroll 4
    for (int i = 0; i < LC; i++) {
        float delta = dptr[l];
        float Bv = bptr[bofs];
        float Cv = cptr[bofs];
        float xv = xptr[s];
        float dA = ex2f(delta * a2);
        h = fmaf(dA, h, delta * xv * Bv);
        float v = h * Cv;
        v += __shfl_xor_sync(0xffffffffu, v, 1);
        v += __shfl_xor_sync(0xffffffffu, v, 2);
        v += __shfl_xor_sync(0xffffffffu, v, 4);
        v += __shfl_xor_sync(0xffffffffu, v, 8);
        if (n == 0) yptr[s] = fmaf(Dv, xv, v);
        l++; bofs += NS;
        if (K == 0) s++;
        else if (K == 2) s--;
        else if (K == 1) { r56++; s += HW; if (r56 == HW) { r56 = 0; s -= L - 1; } }
        else             { r56++; s -= HW; if (r56 == HW) { r56 = 0; s += L - 1; } }
    }
}

__global__ void k_scanC(const float* __restrict__ alogs, const float* __restrict__ ds) {
    const int k = blockIdx.x / 588;
    const int bid = blockIdx.x % 588;
    const int gl = bid * 16 + (threadIdx.x >> 4);
    const int n = threadIdx.x & 15;
    const int d = gl / NC, c = gl % NC;
    const int kd = k * DI + d;
    switch (k) {
        case 0: scanC_body<0>(kd, d, c, n, alogs, ds); break;
        case 1: scanC_body<1>(kd, d, c, n, alogs, ds); break;
        case 2: scanC_body<2>(kd, d, c, n, alogs, ds); break;
        default: scanC_body<3>(kd, d, c, n, alogs, ds); break;
    }
}

// ---------------- K5: merge 4 dirs + LayerNorm + z-gate + out_proj --------
__global__ void k_merge_out(const float* __restrict__ lnw, const float* __restrict__ lnb,
                            const float* __restrict__ ow, float* __restrict__ out) {
    __shared__ float yt[DI * 33];
    __shared__ float red1[256], red2[256];
    __shared__ float mu_s[32], rs_s[32];
    const int s0 = blockIdx.x * 32;
    const int tid = threadIdx.x;

    for (int e = tid; e < DI * 32; e += 256) {
        int d = e >> 5, ls = e & 31;
        int s = s0 + ls;
        float v = g_y4[d * L + s] + g_y4[(DI + d) * L + s] +
                  g_y4[(2 * DI + d) * L + s] + g_y4[(3 * DI + d) * L + s];
        yt[d * 33 + ls] = v;
    }
    __syncthreads();
    {
        int j = tid >> 5, ls = tid & 31;
        float s1 = 0.f, s2 = 0.f;
        for (int d = j; d < DI; d += 8) {
            float v = yt[d * 33 + ls];
            s1 += v; s2 += v * v;
        }
        red1[tid] = s1; red2[tid] = s2;
    }
    __syncthreads();
    if (tid < 32) {
        float s1 = 0.f, s2 = 0.f;
        #pragma unroll
        for (int j = 0; j < 8; j++) { s1 += red1[j * 32 + tid]; s2 += red2[j * 32 + tid]; }
        float mu = s1 / DI;
        float var = s2 / DI - mu * mu;
        mu_s[tid] = mu;
        rs_s[tid] = rsqrtf(var + 1e-5f);
    }
    __syncthreads();
    for (int e = tid; e < DI * 32; e += 256) {
        int ls = e / DI, d = e % DI;
        float v = yt[d * 33 + ls];
        v = (v - mu_s[ls]) * rs_s[ls] * lnw[d] + lnb[d];
        v *= g_z[(s0 + ls) * DI + d];
        yt[d * 33 + ls] = v;
    }
    __syncthreads();
    {
        int ls = tid & 31, og = tid >> 5;
        float acc[12] = {};
        for (int d = 0; d < DI; d++) {
            float yv = yt[d * 33 + ls];
            #pragma unroll
            for (int j = 0; j < 12; j++) acc[j] += yv * ow[(og + 8 * j) * DI + d];
        }
        #pragma unroll
        for (int j = 0; j < 12; j++) out[(s0 + ls) * DM + og + 8 * j] = acc[j];
    }
}

// ---------------- launch ---------------------------------------------------
extern "C" void kernel_launch(void* const* d_in, const int* in_sizes, int n_in,
                              void* d_out, int out_size) {
    const float* x     = (const float*)d_in[0];
    const float* inw   = (const float*)d_in[1];
    const float* cw    = (const float*)d_in[2];
    const float* cb    = (const float*)d_in[3];
    const float* xpw   = (const float*)d_in[4];
    const float* dtw   = (const float*)d_in[5];
    const float* dtb   = (const float*)d_in[6];
    const float* alogs = (const float*)d_in[7];
    const float* ds    = (const float*)d_in[8];
    const float* lnw   = (const float*)d_in[9];
    const float* lnb   = (const float*)d_in[10];
    const float* ow    = (const float*)d_in[11];
    float* out = (float*)d_out;

    k_inproj<<<dim3(98, 6), 256>>>(x, inw);
    k_conv<<<dim3(192, 14), dim3(56, 4)>>>(cw, cb);
    k_xdbl<<<49, 256>>>(xpw);
    k_delta<<<768, 256>>>(dtw, dtb);
    k_scanA<<<2352, 256>>>(alogs);
    k_scanB<<<48, 256>>>();
    k_scanC<<<2352, 256>>>(alogs, ds);
    k_merge_out<<<98, 256>>>(lnw, lnb, ow, out);
}

// round 4
// speedup vs baseline: 4.6579x; 1.0849x over previous
#include <cuda_runtime.h>
#include <math.h>

#define L    3136
#define HW   56
#define DM   96
#define DI   192
#define NS   16
#define KDIR 4
#define RR   6
#define NC   49
#define LC   64

// ---------------- scratch (device globals; no allocation) ----------------
__device__ float g_xc[DI * L];          // conv input, channel-major [d][s]
__device__ float g_z[L * DI];           // gate, pixel-major [s][d]
__device__ float g_xconv[DI * L];       // conv output, channel-major [d][s]
__device__ float g_dts[KDIR * RR * L];  // low-rank dt, scan order [k*6+r][l]
__device__ float g_Bs[KDIR * L * NS];   // scan order [(k*L+l)*16+n]
__device__ float g_Cs[KDIR * L * NS];
__device__ float g_delta[KDIR * DI * L];// scan order [kd][l]
__device__ float g_P[KDIR * DI * NC * NS];   // per-chunk prod(dA)
__device__ float g_Hc[KDIR * DI * NC * NS];  // per-chunk h_end -> h_in
__device__ float g_y4[KDIR * DI * L];   // per-direction y at SPATIAL index

__device__ __forceinline__ float siluf(float x) { return x / (1.f + __expf(-x)); }
__device__ __forceinline__ float softplusf(float x) {
    return x > 20.f ? x : __logf(1.f + __expf(x));
}
__device__ __forceinline__ float ex2f(float x) {
    float r;
    asm("ex2.approx.f32 %0, %1;" : "=f"(r) : "f"(x));
    return r;
}
#define LOG2E 1.4426950408889634f

// ---------------- K1: in_proj GEMM (L x 96) @ (96 x 384), split xc/z ------
__global__ void k_inproj(const float* __restrict__ x, const float* __restrict__ w) {
    __shared__ float As[32 * 96];
    __shared__ float Bs[96 * 65];
    __shared__ float Csh[64 * 33];
    const int l0 = blockIdx.x * 32;
    const int o0 = blockIdx.y * 64;
    const int tid = threadIdx.x;

    for (int e = tid; e < 32 * 96; e += 256)
        As[e] = x[(l0 + e / 96) * 96 + (e % 96)];
    for (int e = tid; e < 96 * 64; e += 256) {
        int o = e / 96, c = e % 96;
        Bs[c * 65 + o] = w[(o0 + o) * 96 + c];
    }
    __syncthreads();

    const int tl = tid >> 5, to = tid & 31;
    float acc[4][2] = {};
    #pragma unroll 8
    for (int kk = 0; kk < 96; kk++) {
        float b0 = Bs[kk * 65 + to];
        float b1 = Bs[kk * 65 + to + 32];
        #pragma unroll
        for (int i = 0; i < 4; i++) {
            float a = As[(tl * 4 + i) * 96 + kk];
            acc[i][0] += a * b0;
            acc[i][1] += a * b1;
        }
    }
    __syncthreads();
    #pragma unroll
    for (int i = 0; i < 4; i++) {
        Csh[to * 33 + tl * 4 + i] = acc[i][0];
        Csh[(to + 32) * 33 + tl * 4 + i] = acc[i][1];
    }
    __syncthreads();

    for (int e = tid; e < 2048; e += 256) {
        int ol = e >> 5, l = e & 31;
        int o = o0 + ol;
        if (o < DI) g_xc[o * L + l0 + l] = Csh[ol * 33 + l];
    }
    for (int e = tid; e < 2048; e += 256) {
        int l = e >> 6, ol = e & 63;
        int o = o0 + ol;
        if (o >= DI) {
            float v = Csh[ol * 33 + l];
            g_z[(l0 + l) * DI + (o - DI)] = siluf(v);
        }
    }
}

// ---------------- K2: depthwise 3x3 conv SAME + silu ----------------------
__global__ void k_conv(const float* __restrict__ cw, const float* __restrict__ cb) {
    const int d = blockIdx.x;
    const int h = blockIdx.y * 4 + threadIdx.y;
    const int w = threadIdx.x;
    float wgt[9];
    #pragma unroll
    for (int i = 0; i < 9; i++) wgt[i] = cw[d * 9 + i];
    float acc = cb[d];
    const float* base = g_xc + d * L;
    #pragma unroll
    for (int i = 0; i < 3; i++) {
        int hh = h + i - 1;
        if (hh < 0 || hh >= HW) continue;
        #pragma unroll
        for (int j = 0; j < 3; j++) {
            int ww = w + j - 1;
            if (ww < 0 || ww >= HW) continue;
            acc += base[hh * HW + ww] * wgt[i * 3 + j];
        }
    }
    g_xconv[d * L + h * HW + w] = siluf(acc);
}

// ---------------- K3a: x_dbl projection GEMM, scatter into scan order -----
#define XD_KD 48
__global__ void k_xdbl(const float* __restrict__ xpw) {
    __shared__ float xs[XD_KD * 64];    // [dd][ss]
    __shared__ float ws[160 * XD_KD];   // [row][dd], rows 152..159 zero
    const int s0 = blockIdx.x * 64;
    const int tid = threadIdx.x;
    const int tx = tid & 31;
    const int r0 = (tid >> 5) * 20;

    float acc[20][2];
    #pragma unroll
    for (int j = 0; j < 20; j++) { acc[j][0] = 0.f; acc[j][1] = 0.f; }

    for (int d0 = 0; d0 < DI; d0 += XD_KD) {
        __syncthreads();
        #pragma unroll
        for (int e = tid; e < XD_KD * 64; e += 256) {
            int dd = e >> 6, ss = e & 63;
            xs[e] = g_xconv[(d0 + dd) * L + s0 + ss];
        }
        for (int e = tid; e < 160 * XD_KD; e += 256) {
            int row = e / XD_KD, dd = e % XD_KD;
            ws[e] = (row < 152) ? xpw[row * DI + d0 + dd] : 0.f;
        }
        __syncthreads();
        #pragma unroll 4
        for (int dd = 0; dd < XD_KD; dd++) {
            float xv0 = xs[dd * 64 + tx];
            float xv1 = xs[dd * 64 + tx + 32];
            #pragma unroll
            for (int j = 0; j < 20; j++) {
                float wv = ws[(r0 + j) * XD_KD + dd];
                acc[j][0] += wv * xv0;
                acc[j][1] += wv * xv1;
            }
        }
    }

    #pragma unroll
    for (int j = 0; j < 20; j++) {
        int row = r0 + j;
        if (row >= 152) break;
        int k = row / 38, r = row % 38;
        #pragma unroll
        for (int c = 0; c < 2; c++) {
            int s = s0 + tx + 32 * c;
            int hs = s / HW, wsp = s % HW;
            int tpos = wsp * HW + hs;
            int lp = (k == 0) ? s : (k == 1) ? tpos : (k == 2) ? (L - 1 - s) : (L - 1 - tpos);
            float v = acc[j][c];
            if (r < RR)            g_dts[(k * RR + r) * L + lp] = v;
            else if (r < RR + NS)  g_Bs[(k * L + lp) * NS + (r - RR)] = v;
            else                   g_Cs[(k * L + lp) * NS + (r - RR - NS)] = v;
        }
    }
}

// ---------------- K3b: dt projection + softplus -> delta, float4 ----------
__global__ void k_delta(const float* __restrict__ dtw, const float* __restrict__ dtb) {
    const int kd = blockIdx.x;   // 0..767
    const int k = kd / DI;
    float wr[6];
    #pragma unroll
    for (int r = 0; r < 6; r++) wr[r] = dtw[kd * 6 + r];
    const float b = dtb[kd];
    const float4* dbase = (const float4*)(g_dts + k * RR * L);
    float4* obase = (float4*)(g_delta + kd * L);
    #pragma unroll 2
    for (int v = threadIdx.x; v < L / 4; v += 256) {
        float a0 = b, a1 = b, a2 = b, a3 = b;
        #pragma unroll
        for (int r = 0; r < 6; r++) {
            float4 t = dbase[r * (L / 4) + v];
            a0 += t.x * wr[r]; a1 += t.y * wr[r];
            a2 += t.z * wr[r]; a3 += t.w * wr[r];
        }
        float4 o;
        o.x = softplusf(a0); o.y = softplusf(a1);
        o.z = softplusf(a2); o.w = softplusf(a3);
        obase[v] = o;
    }
}

// ---------------- scan kernels: 4 lanes/group, 4 states/lane ---------------
// scan position l -> spatial index s:
//  K=0: s=l   K=1: s=(l%56)*56+l/56   K=2: s=L-1-l   K=3: s=L-1-((l%56)*56+l/56)

template<int K>
__device__ __forceinline__ void scanA_body(int kd, int d, int c, int n4,
                                           const float* __restrict__ alogs) {
    float4 al = *(const float4*)&alogs[kd * NS + n4 * 4];
    float a20 = -__expf(al.x) * LOG2E;
    float a21 = -__expf(al.y) * LOG2E;
    float a22 = -__expf(al.z) * LOG2E;
    float a23 = -__expf(al.w) * LOG2E;
    const float* __restrict__ dptr = g_delta + kd * L;
    const float* __restrict__ bbase = g_Bs + K * L * NS + n4 * 4;
    const float* __restrict__ xptr = g_xconv + d * L;
    int l = c * LC;
    int r56 = l % HW;
    int s;
    if (K == 0) s = l;
    else if (K == 1) s = r56 * HW + l / HW;
    else if (K == 2) s = L - 1 - l;
    else s = L - 1 - (r56 * HW + l / HW);

    float h0 = 0.f, h1 = 0.f, h2 = 0.f, h3 = 0.f, sd = 0.f;
    #pragma unroll 4
    for (int i = 0; i < LC; i++) {
        float delta = dptr[l];
        float4 Bv = *(const float4*)&bbase[l * NS];
        float xv = xptr[s];
        float dx = delta * xv;
        h0 = fmaf(ex2f(delta * a20), h0, dx * Bv.x);
        h1 = fmaf(ex2f(delta * a21), h1, dx * Bv.y);
        h2 = fmaf(ex2f(delta * a22), h2, dx * Bv.z);
        h3 = fmaf(ex2f(delta * a23), h3, dx * Bv.w);
        sd += delta;
        l++;
        if (K == 0) s++;
        else if (K == 2) s--;
        else if (K == 1) { r56++; s += HW; if (r56 == HW) { r56 = 0; s -= L - 1; } }
        else             { r56++; s -= HW; if (r56 == HW) { r56 = 0; s += L - 1; } }
    }
    int idx = (kd * NC + c) * NS + n4 * 4;
    float4 P; P.x = ex2f(a20 * sd); P.y = ex2f(a21 * sd);
    P.z = ex2f(a22 * sd); P.w = ex2f(a23 * sd);
    float4 H; H.x = h0; H.y = h1; H.z = h2; H.w = h3;
    *(float4*)&g_P[idx] = P;
    *(float4*)&g_Hc[idx] = H;
}

__global__ void k_scanA(const float* __restrict__ alogs) {
    const int k = blockIdx.x / 147;              // 147 blocks per direction
    const int gl = (blockIdx.x % 147) * 64 + (threadIdx.x >> 2);
    const int n4 = threadIdx.x & 3;
    const int d = gl / NC, c = gl % NC;
    const int kd = k * DI + d;
    switch (k) {
        case 0: scanA_body<0>(kd, d, c, n4, alogs); break;
        case 1: scanA_body<1>(kd, d, c, n4, alogs); break;
        case 2: scanA_body<2>(kd, d, c, n4, alogs); break;
        default: scanA_body<3>(kd, d, c, n4, alogs); break;
    }
}

// ---------------- K4b: carry scan across chunks (49 steps), float4 --------
__global__ void k_scanB() {
    const int t = blockIdx.x * blockDim.x + threadIdx.x;  // 3072 threads
    const int kd = t >> 2, n4 = t & 3;
    float4 carry = {0.f, 0.f, 0.f, 0.f};
    const int base = kd * NC * NS + n4 * 4;
    for (int c = 0; c < NC; c++) {
        int idx = base + c * NS;
        float4 p = *(float4*)&g_P[idx];
        float4 he = *(float4*)&g_Hc[idx];
        *(float4*)&g_Hc[idx] = carry;
        carry.x = fmaf(p.x, carry.x, he.x);
        carry.y = fmaf(p.y, carry.y, he.y);
        carry.z = fmaf(p.z, carry.z, he.z);
        carry.w = fmaf(p.w, carry.w, he.w);
    }
}

// ---------------- K4c: chunk scan pass C, emit y at spatial index ---------
template<int K>
__device__ __forceinline__ void scanC_body(int kd, int d, int c, int n4,
                                           const float* __restrict__ alogs,
                                           const float* __restrict__ ds) {
    float4 al = *(const float4*)&alogs[kd * NS + n4 * 4];
    float a20 = -__expf(al.x) * LOG2E;
    float a21 = -__expf(al.y) * LOG2E;
    float a22 = -__expf(al.z) * LOG2E;
    float a23 = -__expf(al.w) * LOG2E;
    const float Dv = ds[kd];
    float4 H = *(const float4*)&g_Hc[(kd * NC + c) * NS + n4 * 4];
    float h0 = H.x, h1 = H.y, h2 = H.z, h3 = H.w;
    const float* __restrict__ dptr = g_delta + kd * L;
    const float* __restrict__ bbase = g_Bs + K * L * NS + n4 * 4;
    const float* __restrict__ cbase = g_Cs + K * L * NS + n4 * 4;
    const float* __restrict__ xptr = g_xconv + d * L;
    float* __restrict__ yptr = g_y4 + kd * L;
    int l = c * LC;
    int r56 = l % HW;
    int s;
    if (K == 0) s = l;
    else if (K == 1) s = r56 * HW + l / HW;
    else if (K == 2) s = L - 1 - l;
    else s = L - 1 - (r56 * HW + l / HW);

    #pragma unroll 4
    for (int i = 0; i < LC; i++) {
        float delta = dptr[l];
        float4 Bv = *(const float4*)&bbase[l * NS];
        float4 Cv = *(const float4*)&cbase[l * NS];
        float xv = xptr[s];
        float dx = delta * xv;
        h0 = fmaf(ex2f(delta * a20), h0, dx * Bv.x);
        h1 = fmaf(ex2f(delta * a21), h1, dx * Bv.y);
        h2 = fmaf(ex2f(delta * a22), h2, dx * Bv.z);
        h3 = fmaf(ex2f(delta * a23), h3, dx * Bv.w);
        float v = h0 * Cv.x + h1 * Cv.y + h2 * Cv.z + h3 * Cv.w;
        v += __shfl_xor_sync(0xffffffffu, v, 1);
        v += __shfl_xor_sync(0xffffffffu, v, 2);
        if (n4 == 0) yptr[s] = fmaf(Dv, xv, v);
        l++;
        if (K == 0) s++;
        else if (K == 2) s--;
        else if (K == 1) { r56++; s += HW; if (r56 == HW) { r56 = 0; s -= L - 1; } }
        else             { r56++; s -= HW; if (r56 == HW) { r56 = 0; s += L - 1; } }
    }
}

__global__ void k_scanC(const float* __restrict__ alogs, const float* __restrict__ ds) {
    const int k = blockIdx.x / 147;
    const int gl = (blockIdx.x % 147) * 64 + (threadIdx.x >> 2);
    const int n4 = threadIdx.x & 3;
    const int d = gl / NC, c = gl % NC;
    const int kd = k * DI + d;
    switch (k) {
        case 0: scanC_body<0>(kd, d, c, n4, alogs, ds); break;
        case 1: scanC_body<1>(kd, d, c, n4, alogs, ds); break;
        case 2: scanC_body<2>(kd, d, c, n4, alogs, ds); break;
        default: scanC_body<3>(kd, d, c, n4, alogs, ds); break;
    }
}

// ---------------- K5: merge 4 dirs + LayerNorm + z-gate + out_proj --------
__global__ void k_merge_out(const float* __restrict__ lnw, const float* __restrict__ lnb,
                            const float* __restrict__ ow, float* __restrict__ out) {
    __shared__ float yt[DI * 33];
    __shared__ float red1[256], red2[256];
    __shared__ float mu_s[32], rs_s[32];
    const int s0 = blockIdx.x * 32;
    const int tid = threadIdx.x;

    for (int e = tid; e < DI * 32; e += 256) {
        int d = e >> 5, ls = e & 31;
        int s = s0 + ls;
        float v = g_y4[d * L + s] + g_y4[(DI + d) * L + s] +
                  g_y4[(2 * DI + d) * L + s] + g_y4[(3 * DI + d) * L + s];
        yt[d * 33 + ls] = v;
    }
    __syncthreads();
    {
        int j = tid >> 5, ls = tid & 31;
        float s1 = 0.f, s2 = 0.f;
        for (int d = j; d < DI; d += 8) {
            float v = yt[d * 33 + ls];
            s1 += v; s2 += v * v;
        }
        red1[tid] = s1; red2[tid] = s2;
    }
    __syncthreads();
    if (tid < 32) {
        float s1 = 0.f, s2 = 0.f;
        #pragma unroll
        for (int j = 0; j < 8; j++) { s1 += red1[j * 32 + tid]; s2 += red2[j * 32 + tid]; }
        float mu = s1 / DI;
        float var = s2 / DI - mu * mu;
        mu_s[tid] = mu;
        rs_s[tid] = rsqrtf(var + 1e-5f);
    }
    __syncthreads();
    for (int e = tid; e < DI * 32; e += 256) {
        int ls = e / DI, d = e % DI;
        float v = yt[d * 33 + ls];
        v = (v - mu_s[ls]) * rs_s[ls] * lnw[d] + lnb[d];
        v *= g_z[(s0 + ls) * DI + d];
        yt[d * 33 + ls] = v;
    }
    __syncthreads();
    {
        int ls = tid & 31, og = tid >> 5;
        float acc[12] = {};
        for (int d = 0; d < DI; d++) {
            float yv = yt[d * 33 + ls];
            #pragma unroll
            for (int j = 0; j < 12; j++) acc[j] += yv * __ldg(&ow[(og + 8 * j) * DI + d]);
        }
        #pragma unroll
        for (int j = 0; j < 12; j++) out[(s0 + ls) * DM + og + 8 * j] = acc[j];
    }
}

// ---------------- launch ---------------------------------------------------
extern "C" void kernel_launch(void* const* d_in, const int* in_sizes, int n_in,
                              void* d_out, int out_size) {
    const float* x     = (const float*)d_in[0];
    const float* inw   = (const float*)d_in[1];
    const float* cw    = (const float*)d_in[2];
    const float* cb    = (const float*)d_in[3];
    const float* xpw   = (const float*)d_in[4];
    const float* dtw   = (const float*)d_in[5];
    const float* dtb   = (const float*)d_in[6];
    const float* alogs = (const float*)d_in[7];
    const float* ds    = (const float*)d_in[8];
    const float* lnw   = (const float*)d_in[9];
    const float* lnb   = (const float*)d_in[10];
    const float* ow    = (const float*)d_in[11];
    float* out = (float*)d_out;

    k_inproj<<<dim3(98, 6), 256>>>(x, inw);
    k_conv<<<dim3(192, 14), dim3(56, 4)>>>(cw, cb);
    k_xdbl<<<49, 256>>>(xpw);
    k_delta<<<768, 256>>>(dtw, dtb);
    k_scanA<<<588, 256>>>(alogs);
    k_scanB<<<12, 256>>>();
    k_scanC<<<588, 256>>>(alogs, ds);
    k_merge_out<<<98, 256>>>(lnw, lnb, ow, out);
}

// round 5
// speedup vs baseline: 4.8100x; 1.0327x over previous
#include <cuda_runtime.h>
#include <math.h>

#define L    3136
#define HW   56
#define DM   96
#define DI   192
#define NS   16
#define KDIR 4
#define RR   6
#define NC   49
#define LC   64

// ---------------- scratch (device globals; no allocation) ----------------
__device__ float g_xc[DI * L];           // conv input, channel-major [d][s]
__device__ float g_z[L * DI];            // gate, pixel-major [s][d]
__device__ float g_xconv[DI * L];        // conv output, channel-major [d][s]
__device__ float g_xt[DI * L];           // transposed xconv: xt[d][j] = xconv[d][(j%56)*56+j/56]
__device__ float g_dts[KDIR * RR * L];   // low-rank dt, scan order [k*6+r][l]
__device__ float g_Bs[KDIR * L * NS];    // scan order [(k*L+l)*16+n]
__device__ float g_Cs[KDIR * L * NS];
__device__ float2 g_dx[KDIR * DI * L];   // packed (delta, x) in scan order [kd][l]
__device__ float g_P[KDIR * DI * NC * NS];   // per-chunk prod(dA)
__device__ float g_Hc[KDIR * DI * NC * NS];  // per-chunk h_end -> h_in
__device__ float g_y4[KDIR * DI * L];    // per-direction y at SPATIAL index

__device__ __forceinline__ float siluf(float x) { return x / (1.f + __expf(-x)); }
__device__ __forceinline__ float softplusf(float x) {
    return x > 20.f ? x : __logf(1.f + __expf(x));
}
__device__ __forceinline__ float ex2f(float x) {
    float r;
    asm("ex2.approx.f32 %0, %1;" : "=f"(r) : "f"(x));
    return r;
}
#define LOG2E 1.4426950408889634f

// ---------------- K1: in_proj GEMM (L x 96) @ (96 x 384), split xc/z ------
__global__ void k_inproj(const float* __restrict__ x, const float* __restrict__ w) {
    __shared__ float As[32 * 96];
    __shared__ float Bs[96 * 65];
    __shared__ float Csh[64 * 33];
    const int l0 = blockIdx.x * 32;
    const int o0 = blockIdx.y * 64;
    const int tid = threadIdx.x;

    for (int e = tid; e < 32 * 96; e += 256)
        As[e] = x[(l0 + e / 96) * 96 + (e % 96)];
    for (int e = tid; e < 96 * 64; e += 256) {
        int o = e / 96, c = e % 96;
        Bs[c * 65 + o] = w[(o0 + o) * 96 + c];
    }
    __syncthreads();

    const int tl = tid >> 5, to = tid & 31;
    float acc[4][2] = {};
    #pragma unroll 8
    for (int kk = 0; kk < 96; kk++) {
        float b0 = Bs[kk * 65 + to];
        float b1 = Bs[kk * 65 + to + 32];
        #pragma unroll
        for (int i = 0; i < 4; i++) {
            float a = As[(tl * 4 + i) * 96 + kk];
            acc[i][0] += a * b0;
            acc[i][1] += a * b1;
        }
    }
    __syncthreads();
    #pragma unroll
    for (int i = 0; i < 4; i++) {
        Csh[to * 33 + tl * 4 + i] = acc[i][0];
        Csh[(to + 32) * 33 + tl * 4 + i] = acc[i][1];
    }
    __syncthreads();

    for (int e = tid; e < 2048; e += 256) {
        int ol = e >> 5, l = e & 31;
        int o = o0 + ol;
        if (o < DI) g_xc[o * L + l0 + l] = Csh[ol * 33 + l];
    }
    for (int e = tid; e < 2048; e += 256) {
        int l = e >> 6, ol = e & 63;
        int o = o0 + ol;
        if (o >= DI) {
            float v = Csh[ol * 33 + l];
            g_z[(l0 + l) * DI + (o - DI)] = siluf(v);
        }
    }
}

// ---------------- K2: depthwise 3x3 conv SAME + silu ----------------------
__global__ void k_conv(const float* __restrict__ cw, const float* __restrict__ cb) {
    const int d = blockIdx.x;
    const int h = blockIdx.y * 4 + threadIdx.y;
    const int w = threadIdx.x;
    float wgt[9];
    #pragma unroll
    for (int i = 0; i < 9; i++) wgt[i] = cw[d * 9 + i];
    float acc = cb[d];
    const float* base = g_xc + d * L;
    #pragma unroll
    for (int i = 0; i < 3; i++) {
        int hh = h + i - 1;
        if (hh < 0 || hh >= HW) continue;
        #pragma unroll
        for (int j = 0; j < 3; j++) {
            int ww = w + j - 1;
            if (ww < 0 || ww >= HW) continue;
            acc += base[hh * HW + ww] * wgt[i * 3 + j];
        }
    }
    g_xconv[d * L + h * HW + w] = siluf(acc);
}

// ---------------- K2b: transpose xconv -> g_xt -----------------------------
__global__ void k_xt() {
    __shared__ float t[56][57];
    const int d = blockIdx.x;
    const int tid = threadIdx.x;
    const float* src = g_xconv + d * L;
    float* dst = g_xt + d * L;
    for (int e = tid; e < L; e += 256) t[e / 56][e % 56] = src[e];
    __syncthreads();
    for (int e = tid; e < L; e += 256) dst[e] = t[e % 56][e / 56];
}

// ---------------- K3a: x_dbl projection GEMM, scatter into scan order -----
#define XD_KD 48
__global__ void k_xdbl(const float* __restrict__ xpw) {
    __shared__ float xs[XD_KD * 32];    // [dd][ss]
    __shared__ float ws[160 * XD_KD];   // [row][dd], rows 152..159 zero
    const int s0 = blockIdx.x * 32;
    const int tid = threadIdx.x;
    const int tx = tid & 31;
    const int r0 = (tid >> 5) * 20;

    float acc[20];
    #pragma unroll
    for (int j = 0; j < 20; j++) acc[j] = 0.f;

    for (int d0 = 0; d0 < DI; d0 += XD_KD) {
        __syncthreads();
        #pragma unroll
        for (int e = tid; e < XD_KD * 32; e += 256) {
            int dd = e >> 5, ss = e & 31;
            xs[e] = g_xconv[(d0 + dd) * L + s0 + ss];
        }
        for (int e = tid; e < 160 * XD_KD; e += 256) {
            int row = e / XD_KD, dd = e % XD_KD;
            ws[e] = (row < 152) ? xpw[row * DI + d0 + dd] : 0.f;
        }
        __syncthreads();
        #pragma unroll 4
        for (int dd = 0; dd < XD_KD; dd++) {
            float xv0 = xs[dd * 32 + tx];
            #pragma unroll
            for (int j = 0; j < 20; j++)
                acc[j] += ws[(r0 + j) * XD_KD + dd] * xv0;
        }
    }

    #pragma unroll
    for (int j = 0; j < 20; j++) {
        int row = r0 + j;
        if (row >= 152) break;
        int k = row / 38, r = row % 38;
        int s = s0 + tx;
        int hs = s / HW, wsp = s % HW;
        int tpos = wsp * HW + hs;
        int lp = (k == 0) ? s : (k == 1) ? tpos : (k == 2) ? (L - 1 - s) : (L - 1 - tpos);
        float v = acc[j];
        if (r < RR)            g_dts[(k * RR + r) * L + lp] = v;
        else if (r < RR + NS)  g_Bs[(k * L + lp) * NS + (r - RR)] = v;
        else                   g_Cs[(k * L + lp) * NS + (r - RR - NS)] = v;
    }
}

// ---------------- K3b: delta + x packing -> g_dx ---------------------------
// grid: x = 28 (k*7 + ltile), y = 4 (dgroup of 48). ltile = 448.
__global__ void k_dx(const float* __restrict__ dtw, const float* __restrict__ dtb) {
    __shared__ float sm[RR][448];
    const int k = blockIdx.x / 7;
    const int l0 = (blockIdx.x % 7) * 448;
    const int tid = threadIdx.x;
    for (int e = tid; e < RR * 448; e += 256)
        sm[e / 448][e % 448] = g_dts[(k * RR + e / 448) * L + l0 + (e % 448)];
    __syncthreads();

    const int d0 = blockIdx.y * 48;
    const bool rev = (k >= 2);
    for (int d = d0; d < d0 + 48; d++) {
        const int kd = k * DI + d;
        float wr[6];
        #pragma unroll
        for (int r = 0; r < 6; r++) wr[r] = dtw[kd * 6 + r];
        const float b = dtb[kd];
        const float* xsrc = ((k & 1) == 0) ? (g_xconv + d * L) : (g_xt + d * L);
        float2* out = g_dx + kd * L;
        #pragma unroll 2
        for (int i = tid; i < 448; i += 256) {
            int l = l0 + i;
            float acc = b;
            #pragma unroll
            for (int r = 0; r < 6; r++) acc = fmaf(sm[r][i], wr[r], acc);
            float xv = rev ? xsrc[L - 1 - l] : xsrc[l];
            float2 o; o.x = softplusf(acc); o.y = xv;
            out[l] = o;
        }
    }
}

// ---------------- scan kernels: 4 lanes/group, 4 states/lane ---------------
template<int K>
__device__ __forceinline__ void scanA_body(int kd, int c, int n4,
                                           const float* __restrict__ alogs) {
    float4 al = *(const float4*)&alogs[kd * NS + n4 * 4];
    float a20 = -__expf(al.x) * LOG2E;
    float a21 = -__expf(al.y) * LOG2E;
    float a22 = -__expf(al.z) * LOG2E;
    float a23 = -__expf(al.w) * LOG2E;
    const float4* __restrict__ dx = (const float4*)(g_dx + kd * L + c * LC);
    const float* __restrict__ bbase = g_Bs + K * L * NS + n4 * 4;
    int l = c * LC;

    float h0 = 0.f, h1 = 0.f, h2 = 0.f, h3 = 0.f, sd = 0.f;
    #pragma unroll 4
    for (int i = 0; i < LC / 2; i++) {
        float4 t = dx[i];   // (delta0, x0, delta1, x1)
        {
            float4 Bv = *(const float4*)&bbase[l * NS];
            float dxv = t.x * t.y;
            h0 = fmaf(ex2f(t.x * a20), h0, dxv * Bv.x);
            h1 = fmaf(ex2f(t.x * a21), h1, dxv * Bv.y);
            h2 = fmaf(ex2f(t.x * a22), h2, dxv * Bv.z);
            h3 = fmaf(ex2f(t.x * a23), h3, dxv * Bv.w);
            sd += t.x; l++;
        }
        {
            float4 Bv = *(const float4*)&bbase[l * NS];
            float dxv = t.z * t.w;
            h0 = fmaf(ex2f(t.z * a20), h0, dxv * Bv.x);
            h1 = fmaf(ex2f(t.z * a21), h1, dxv * Bv.y);
            h2 = fmaf(ex2f(t.z * a22), h2, dxv * Bv.z);
            h3 = fmaf(ex2f(t.z * a23), h3, dxv * Bv.w);
            sd += t.z; l++;
        }
    }
    int idx = (kd * NC + c) * NS + n4 * 4;
    float4 P; P.x = ex2f(a20 * sd); P.y = ex2f(a21 * sd);
    P.z = ex2f(a22 * sd); P.w = ex2f(a23 * sd);
    float4 H; H.x = h0; H.y = h1; H.z = h2; H.w = h3;
    *(float4*)&g_P[idx] = P;
    *(float4*)&g_Hc[idx] = H;
}

__global__ void k_scanA(const float* __restrict__ alogs) {
    const int k = blockIdx.x / 147;              // 147 blocks per direction
    const int gl = (blockIdx.x % 147) * 64 + (threadIdx.x >> 2);
    const int n4 = threadIdx.x & 3;
    const int d = gl / NC, c = gl % NC;
    const int kd = k * DI + d;
    switch (k) {
        case 0: scanA_body<0>(kd, c, n4, alogs); break;
        case 1: scanA_body<1>(kd, c, n4, alogs); break;
        case 2: scanA_body<2>(kd, c, n4, alogs); break;
        default: scanA_body<3>(kd, c, n4, alogs); break;
    }
}

// ---------------- K4b: carry scan across chunks (49 steps), float4 --------
__global__ void k_scanB() {
    const int t = blockIdx.x * blockDim.x + threadIdx.x;  // 3072 threads
    const int kd = t >> 2, n4 = t & 3;
    float4 carry = {0.f, 0.f, 0.f, 0.f};
    const int base = kd * NC * NS + n4 * 4;
    for (int c = 0; c < NC; c++) {
        int idx = base + c * NS;
        float4 p = *(float4*)&g_P[idx];
        float4 he = *(float4*)&g_Hc[idx];
        *(float4*)&g_Hc[idx] = carry;
        carry.x = fmaf(p.x, carry.x, he.x);
        carry.y = fmaf(p.y, carry.y, he.y);
        carry.z = fmaf(p.z, carry.z, he.z);
        carry.w = fmaf(p.w, carry.w, he.w);
    }
}

// ---------------- K4c: chunk scan pass C, emit y at spatial index ---------
template<int K>
__device__ __forceinline__ void scanC_body(int kd, int d, int c, int n4,
                                           const float* __restrict__ alogs,
                                           const float* __restrict__ ds) {
    float4 al = *(const float4*)&alogs[kd * NS + n4 * 4];
    float a20 = -__expf(al.x) * LOG2E;
    float a21 = -__expf(al.y) * LOG2E;
    float a22 = -__expf(al.z) * LOG2E;
    float a23 = -__expf(al.w) * LOG2E;
    const float Dv = ds[kd];
    float4 H = *(const float4*)&g_Hc[(kd * NC + c) * NS + n4 * 4];
    float h0 = H.x, h1 = H.y, h2 = H.z, h3 = H.w;
    const float4* __restrict__ dx = (const float4*)(g_dx + kd * L + c * LC);
    const float* __restrict__ bbase = g_Bs + K * L * NS + n4 * 4;
    const float* __restrict__ cbase = g_Cs + K * L * NS + n4 * 4;
    float* __restrict__ yptr = g_y4 + kd * L;
    int l = c * LC;
    int r56 = l % HW;
    int s;
    if (K == 0) s = l;
    else if (K == 1) s = r56 * HW + l / HW;
    else if (K == 2) s = L - 1 - l;
    else s = L - 1 - (r56 * HW + l / HW);

    #pragma unroll 4
    for (int i = 0; i < LC / 2; i++) {
        float4 t = dx[i];
        #pragma unroll
        for (int half = 0; half < 2; half++) {
            float delta = half ? t.z : t.x;
            float xv    = half ? t.w : t.y;
            float4 Bv = *(const float4*)&bbase[l * NS];
            float4 Cv = *(const float4*)&cbase[l * NS];
            float dxv = delta * xv;
            h0 = fmaf(ex2f(delta * a20), h0, dxv * Bv.x);
            h1 = fmaf(ex2f(delta * a21), h1, dxv * Bv.y);
            h2 = fmaf(ex2f(delta * a22), h2, dxv * Bv.z);
            h3 = fmaf(ex2f(delta * a23), h3, dxv * Bv.w);
            float v = h0 * Cv.x + h1 * Cv.y + h2 * Cv.z + h3 * Cv.w;
            v += __shfl_xor_sync(0xffffffffu, v, 1);
            v += __shfl_xor_sync(0xffffffffu, v, 2);
            if (n4 == 0) yptr[s] = fmaf(Dv, xv, v);
            l++;
            if (K == 0) s++;
            else if (K == 2) s--;
            else if (K == 1) { r56++; s += HW; if (r56 == HW) { r56 = 0; s -= L - 1; } }
            else             { r56++; s -= HW; if (r56 == HW) { r56 = 0; s += L - 1; } }
        }
    }
}

__global__ void k_scanC(const float* __restrict__ alogs, const float* __restrict__ ds) {
    const int k = blockIdx.x / 147;
    const int gl = (blockIdx.x % 147) * 64 + (threadIdx.x >> 2);
    const int n4 = threadIdx.x & 3;
    const int d = gl / NC, c = gl % NC;
    const int kd = k * DI + d;
    switch (k) {
        case 0: scanC_body<0>(kd, d, c, n4, alogs, ds); break;
        case 1: scanC_body<1>(kd, d, c, n4, alogs, ds); break;
        case 2: scanC_body<2>(kd, d, c, n4, alogs, ds); break;
        default: scanC_body<3>(kd, d, c, n4, alogs, ds); break;
    }
}

// ---------------- K5: merge 4 dirs + LayerNorm + z-gate + out_proj --------
__global__ void k_merge_out(const float* __restrict__ lnw, const float* __restrict__ lnb,
                            const float* __restrict__ ow, float* __restrict__ out) {
    __shared__ float yt[DI * 33];
    __shared__ float red1[256], red2[256];
    __shared__ float mu_s[32], rs_s[32];
    const int s0 = blockIdx.x * 32;
    const int tid = threadIdx.x;

    for (int e = tid; e < DI * 32; e += 256) {
        int d = e >> 5, ls = e & 31;
        int s = s0 + ls;
        float v = g_y4[d * L + s] + g_y4[(DI + d) * L + s] +
                  g_y4[(2 * DI + d) * L + s] + g_y4[(3 * DI + d) * L + s];
        yt[d * 33 + ls] = v;
    }
    __syncthreads();
    {
        int j = tid >> 5, ls = tid & 31;
        float s1 = 0.f, s2 = 0.f;
        for (int d = j; d < DI; d += 8) {
            float v = yt[d * 33 + ls];
            s1 += v; s2 += v * v;
        }
        red1[tid] = s1; red2[tid] = s2;
    }
    __syncthreads();
    if (tid < 32) {
        float s1 = 0.f, s2 = 0.f;
        #pragma unroll
        for (int j = 0; j < 8; j++) { s1 += red1[j * 32 + tid]; s2 += red2[j * 32 + tid]; }
        float mu = s1 / DI;
        float var = s2 / DI - mu * mu;
        mu_s[tid] = mu;
        rs_s[tid] = rsqrtf(var + 1e-5f);
    }
    __syncthreads();
    for (int e = tid; e < DI * 32; e += 256) {
        int ls = e / DI, d = e % DI;
        float v = yt[d * 33 + ls];
        v = (v - mu_s[ls]) * rs_s[ls] * lnw[d] + lnb[d];
        v *= g_z[(s0 + ls) * DI + d];
        yt[d * 33 + ls] = v;
    }
    __syncthreads();
    {
        int ls = tid & 31, og = tid >> 5;
        float acc[12] = {};
        for (int d = 0; d < DI; d++) {
            float yv = yt[d * 33 + ls];
            #pragma unroll
            for (int j = 0; j < 12; j++) acc[j] += yv * __ldg(&ow[(og + 8 * j) * DI + d]);
        }
        #pragma unroll
        for (int j = 0; j < 12; j++) out[(s0 + ls) * DM + og + 8 * j] = acc[j];
    }
}

// ---------------- launch ---------------------------------------------------
extern "C" void kernel_launch(void* const* d_in, const int* in_sizes, int n_in,
                              void* d_out, int out_size) {
    const float* x     = (const float*)d_in[0];
    const float* inw   = (const float*)d_in[1];
    const float* cw    = (const float*)d_in[2];
    const float* cb    = (const float*)d_in[3];
    const float* xpw   = (const float*)d_in[4];
    const float* dtw   = (const float*)d_in[5];
    const float* dtb   = (const float*)d_in[6];
    const float* alogs = (const float*)d_in[7];
    const float* ds    = (const float*)d_in[8];
    const float* lnw   = (const float*)d_in[9];
    const float* lnb   = (const float*)d_in[10];
    const float* ow    = (const float*)d_in[11];
    float* out = (float*)d_out;

    k_inproj<<<dim3(98, 6), 256>>>(x, inw);
    k_conv<<<dim3(192, 14), dim3(56, 4)>>>(cw, cb);
    k_xt<<<192, 256>>>();
    k_xdbl<<<98, 256>>>(xpw);
    k_dx<<<dim3(28, 4), 256>>>(dtw, dtb);
    k_scanA<<<588, 256>>>(alogs);
    k_scanB<<<12, 256>>>();
    k_scanC<<<588, 256>>>(alogs, ds);
    k_merge_out<<<98, 256>>>(lnw, lnb, ow, out);
}

// round 6
// speedup vs baseline: 4.8685x; 1.0122x over previous
#include <cuda_runtime.h>
#include <math.h>

#define L    3136
#define HW   56
#define DM   96
#define DI   192
#define NS   16
#define KDIR 4
#define RR   6
#define NC   49
#define LC   64

// ---------------- scratch (device globals; no allocation) ----------------
__device__ float g_xc[DI * L];           // conv input, channel-major [d][s]
__device__ float g_z[L * DI];            // gate, pixel-major [s][d]
__device__ float g_xconv[DI * L];        // conv output, channel-major [d][s]
__device__ float g_xt[DI * L];           // transposed xconv
__device__ float g_dts[KDIR * RR * L];   // low-rank dt, scan order [k*6+r][l]
__device__ float g_Bs[KDIR * L * NS];    // scan order [(k*L+l)*16+n]
__device__ float g_Cs[KDIR * L * NS];
__device__ float2 g_dx[KDIR * DI * L];   // packed (delta, x) in scan order [kd][l]
__device__ float g_P[KDIR * DI * NC * NS];
__device__ float g_Hc[KDIR * DI * NC * NS];
__device__ float g_y4[KDIR * DI * L];    // per-direction y at SPATIAL index

__device__ __forceinline__ float siluf(float x) { return x / (1.f + __expf(-x)); }
__device__ __forceinline__ float softplusf(float x) {
    return x > 20.f ? x : __logf(1.f + __expf(x));
}
__device__ __forceinline__ float ex2f(float x) {
    float r;
    asm("ex2.approx.f32 %0, %1;" : "=f"(r) : "f"(x));
    return r;
}
#define LOG2E 1.4426950408889634f

// ---------------- K1: in_proj GEMM (L x 96) @ (96 x 384), split xc/z ------
__global__ void k_inproj(const float* __restrict__ x, const float* __restrict__ w) {
    __shared__ float As[32 * 96];
    __shared__ float Bs[96 * 65];
    __shared__ float Csh[64 * 33];
    const int l0 = blockIdx.x * 32;
    const int o0 = blockIdx.y * 64;
    const int tid = threadIdx.x;

    for (int e = tid; e < 32 * 96; e += 256)
        As[e] = x[(l0 + e / 96) * 96 + (e % 96)];
    for (int e = tid; e < 96 * 64; e += 256) {
        int o = e / 96, c = e % 96;
        Bs[c * 65 + o] = w[(o0 + o) * 96 + c];
    }
    __syncthreads();

    const int tl = tid >> 5, to = tid & 31;
    float acc[4][2] = {};
    #pragma unroll 8
    for (int kk = 0; kk < 96; kk++) {
        float b0 = Bs[kk * 65 + to];
        float b1 = Bs[kk * 65 + to + 32];
        #pragma unroll
        for (int i = 0; i < 4; i++) {
            float a = As[(tl * 4 + i) * 96 + kk];
            acc[i][0] += a * b0;
            acc[i][1] += a * b1;
        }
    }
    __syncthreads();
    #pragma unroll
    for (int i = 0; i < 4; i++) {
        Csh[to * 33 + tl * 4 + i] = acc[i][0];
        Csh[(to + 32) * 33 + tl * 4 + i] = acc[i][1];
    }
    __syncthreads();

    for (int e = tid; e < 2048; e += 256) {
        int ol = e >> 5, l = e & 31;
        int o = o0 + ol;
        if (o < DI) g_xc[o * L + l0 + l] = Csh[ol * 33 + l];
    }
    for (int e = tid; e < 2048; e += 256) {
        int l = e >> 6, ol = e & 63;
        int o = o0 + ol;
        if (o >= DI) {
            float v = Csh[ol * 33 + l];
            g_z[(l0 + l) * DI + (o - DI)] = siluf(v);
        }
    }
}

// ---------------- K2: depthwise 3x3 conv SAME + silu ----------------------
__global__ void k_conv(const float* __restrict__ cw, const float* __restrict__ cb) {
    const int d = blockIdx.x;
    const int h = blockIdx.y * 4 + threadIdx.y;
    const int w = threadIdx.x;
    float wgt[9];
    #pragma unroll
    for (int i = 0; i < 9; i++) wgt[i] = cw[d * 9 + i];
    float acc = cb[d];
    const float* base = g_xc + d * L;
    #pragma unroll
    for (int i = 0; i < 3; i++) {
        int hh = h + i - 1;
        if (hh < 0 || hh >= HW) continue;
        #pragma unroll
        for (int j = 0; j < 3; j++) {
            int ww = w + j - 1;
            if (ww < 0 || ww >= HW) continue;
            acc += base[hh * HW + ww] * wgt[i * 3 + j];
        }
    }
    g_xconv[d * L + h * HW + w] = siluf(acc);
}

// ---------------- K2b: transpose xconv -> g_xt -----------------------------
__global__ void k_xt() {
    __shared__ float t[56][57];
    const int d = blockIdx.x;
    const int tid = threadIdx.x;
    const float* src = g_xconv + d * L;
    float* dst = g_xt + d * L;
    for (int e = tid; e < L; e += 256) t[e / 56][e % 56] = src[e];
    __syncthreads();
    for (int e = tid; e < L; e += 256) dst[e] = t[e % 56][e / 56];
}

// ---------------- K3a: x_dbl projection GEMM, scatter into scan order -----
// grid (49, 4): blockIdx.y = direction k (38 rows), blockIdx.x = 64-px tile.
// 256 threads: tx = px pair (32), ty = row group (8 x 5 rows, rows 38/39 pad).
#define XD_KC 96
__global__ void k_xdbl(const float* __restrict__ xpw) {
    __shared__ float ws[40 * XD_KC];    // [row][dd]
    __shared__ float xs[XD_KC * 64];    // [dd][ss]
    const int k = blockIdx.y;
    const int s0 = blockIdx.x * 64;
    const int tid = threadIdx.x;
    const int tx = tid & 31;            // px pair
    const int ty = tid >> 5;            // row group
    const int r0 = ty * 5;

    float acc[5][2];
    #pragma unroll
    for (int j = 0; j < 5; j++) { acc[j][0] = 0.f; acc[j][1] = 0.f; }

    for (int d0 = 0; d0 < DI; d0 += XD_KC) {
        __syncthreads();
        for (int e = tid; e < 40 * XD_KC; e += 256) {
            int row = e / XD_KC, dd = e % XD_KC;
            ws[e] = (row < 38) ? xpw[(k * 38 + row) * DI + d0 + dd] : 0.f;
        }
        #pragma unroll
        for (int e = tid; e < XD_KC * 64; e += 256) {
            int dd = e >> 6, ss = e & 63;
            xs[e] = g_xconv[(d0 + dd) * L + s0 + ss];
        }
        __syncthreads();
        #pragma unroll 4
        for (int dd = 0; dd < XD_KC; dd++) {
            float2 xv = *(const float2*)&xs[dd * 64 + tx * 2];
            #pragma unroll
            for (int j = 0; j < 5; j++) {
                float wv = ws[(r0 + j) * XD_KC + dd];
                acc[j][0] = fmaf(wv, xv.x, acc[j][0]);
                acc[j][1] = fmaf(wv, xv.y, acc[j][1]);
            }
        }
    }

    // scatter with direction permutation
    #pragma unroll
    for (int j = 0; j < 5; j++) {
        int r = r0 + j;
        if (r >= 38) break;
        #pragma unroll
        for (int c = 0; c < 2; c++) {
            int s = s0 + tx * 2 + c;
            int hs = s / HW, wsp = s % HW;
            int tpos = wsp * HW + hs;
            int lp = (k == 0) ? s : (k == 1) ? tpos : (k == 2) ? (L - 1 - s) : (L - 1 - tpos);
            float v = acc[j][c];
            if (r < RR)            g_dts[(k * RR + r) * L + lp] = v;
            else if (r < RR + NS)  g_Bs[(k * L + lp) * NS + (r - RR)] = v;
            else                   g_Cs[(k * L + lp) * NS + (r - RR - NS)] = v;
        }
    }
}

// ---------------- K3b: delta + x packing -> g_dx ---------------------------
__global__ void k_dx(const float* __restrict__ dtw, const float* __restrict__ dtb) {
    __shared__ float sm[RR][448];
    const int k = blockIdx.x / 7;
    const int l0 = (blockIdx.x % 7) * 448;
    const int tid = threadIdx.x;
    for (int e = tid; e < RR * 448; e += 256)
        sm[e / 448][e % 448] = g_dts[(k * RR + e / 448) * L + l0 + (e % 448)];
    __syncthreads();

    const int d0 = blockIdx.y * 48;
    const bool rev = (k >= 2);
    for (int d = d0; d < d0 + 48; d++) {
        const int kd = k * DI + d;
        float wr[6];
        #pragma unroll
        for (int r = 0; r < 6; r++) wr[r] = dtw[kd * 6 + r];
        const float b = dtb[kd];
        const float* xsrc = ((k & 1) == 0) ? (g_xconv + d * L) : (g_xt + d * L);
        float2* out = g_dx + kd * L;
        #pragma unroll 2
        for (int i = tid; i < 448; i += 256) {
            int l = l0 + i;
            float acc = b;
            #pragma unroll
            for (int r = 0; r < 6; r++) acc = fmaf(sm[r][i], wr[r], acc);
            float xv = rev ? xsrc[L - 1 - l] : xsrc[l];
            float2 o; o.x = softplusf(acc); o.y = xv;
            out[l] = o;
        }
    }
}

// ---------------- scan kernels: 4 lanes/group, 4 states/lane ---------------
template<int K>
__device__ __forceinline__ void scanA_body(int kd, int c, int n4,
                                           const float* __restrict__ alogs) {
    float4 al = *(const float4*)&alogs[kd * NS + n4 * 4];
    float a20 = -__expf(al.x) * LOG2E;
    float a21 = -__expf(al.y) * LOG2E;
    float a22 = -__expf(al.z) * LOG2E;
    float a23 = -__expf(al.w) * LOG2E;
    const float4* __restrict__ dx = (const float4*)(g_dx + kd * L + c * LC);
    const float* __restrict__ bbase = g_Bs + K * L * NS + n4 * 4;
    int l = c * LC;

    float h0 = 0.f, h1 = 0.f, h2 = 0.f, h3 = 0.f, sd = 0.f;
    #pragma unroll 4
    for (int i = 0; i < LC / 2; i++) {
        float4 t = dx[i];   // (delta0, x0, delta1, x1)
        {
            float4 Bv = *(const float4*)&bbase[l * NS];
            float dxv = t.x * t.y;
            h0 = fmaf(ex2f(t.x * a20), h0, dxv * Bv.x);
            h1 = fmaf(ex2f(t.x * a21), h1, dxv * Bv.y);
            h2 = fmaf(ex2f(t.x * a22), h2, dxv * Bv.z);
            h3 = fmaf(ex2f(t.x * a23), h3, dxv * Bv.w);
            sd += t.x; l++;
        }
        {
            float4 Bv = *(const float4*)&bbase[l * NS];
            float dxv = t.z * t.w;
            h0 = fmaf(ex2f(t.z * a20), h0, dxv * Bv.x);
            h1 = fmaf(ex2f(t.z * a21), h1, dxv * Bv.y);
            h2 = fmaf(ex2f(t.z * a22), h2, dxv * Bv.z);
            h3 = fmaf(ex2f(t.z * a23), h3, dxv * Bv.w);
            sd += t.z; l++;
        }
    }
    int idx = (kd * NC + c) * NS + n4 * 4;
    float4 P; P.x = ex2f(a20 * sd); P.y = ex2f(a21 * sd);
    P.z = ex2f(a22 * sd); P.w = ex2f(a23 * sd);
    float4 H; H.x = h0; H.y = h1; H.z = h2; H.w = h3;
    *(float4*)&g_P[idx] = P;
    *(float4*)&g_Hc[idx] = H;
}

__global__ void k_scanA(const float* __restrict__ alogs) {
    const int k = blockIdx.x / 147;
    const int gl = (blockIdx.x % 147) * 64 + (threadIdx.x >> 2);
    const int n4 = threadIdx.x & 3;
    const int d = gl / NC, c = gl % NC;
    const int kd = k * DI + d;
    switch (k) {
        case 0: scanA_body<0>(kd, c, n4, alogs); break;
        case 1: scanA_body<1>(kd, c, n4, alogs); break;
        case 2: scanA_body<2>(kd, c, n4, alogs); break;
        default: scanA_body<3>(kd, c, n4, alogs); break;
    }
}

// ---------------- K4b: carry scan across chunks (49 steps), float4 --------
__global__ void k_scanB() {
    const int t = blockIdx.x * blockDim.x + threadIdx.x;  // 3072 threads
    const int kd = t >> 2, n4 = t & 3;
    float4 carry = {0.f, 0.f, 0.f, 0.f};
    const int base = kd * NC * NS + n4 * 4;
    for (int c = 0; c < NC; c++) {
        int idx = base + c * NS;
        float4 p = *(float4*)&g_P[idx];
        float4 he = *(float4*)&g_Hc[idx];
        *(float4*)&g_Hc[idx] = carry;
        carry.x = fmaf(p.x, carry.x, he.x);
        carry.y = fmaf(p.y, carry.y, he.y);
        carry.z = fmaf(p.z, carry.z, he.z);
        carry.w = fmaf(p.w, carry.w, he.w);
    }
}

// ---------------- K4c: chunk scan pass C, emit y at spatial index ---------
template<int K>
__device__ __forceinline__ void scanC_body(int kd, int d, int c, int n4,
                                           const float* __restrict__ alogs,
                                           const float* __restrict__ ds) {
    float4 al = *(const float4*)&alogs[kd * NS + n4 * 4];
    float a20 = -__expf(al.x) * LOG2E;
    float a21 = -__expf(al.y) * LOG2E;
    float a22 = -__expf(al.z) * LOG2E;
    float a23 = -__expf(al.w) * LOG2E;
    const float Dv = ds[kd];
    float4 H = *(const float4*)&g_Hc[(kd * NC + c) * NS + n4 * 4];
    float h0 = H.x, h1 = H.y, h2 = H.z, h3 = H.w;
    const float4* __restrict__ dx = (const float4*)(g_dx + kd * L + c * LC);
    const float* __restrict__ bbase = g_Bs + K * L * NS + n4 * 4;
    const float* __restrict__ cbase = g_Cs + K * L * NS + n4 * 4;
    float* __restrict__ yptr = g_y4 + kd * L;
    int l = c * LC;
    int r56 = l % HW;
    int s;
    if (K == 0) s = l;
    else if (K == 1) s = r56 * HW + l / HW;
    else if (K == 2) s = L - 1 - l;
    else s = L - 1 - (r56 * HW + l / HW);

    #pragma unroll 4
    for (int i = 0; i < LC / 2; i++) {
        float4 t = dx[i];
        #pragma unroll
        for (int half = 0; half < 2; half++) {
            float delta = half ? t.z : t.x;
            float xv    = half ? t.w : t.y;
            float4 Bv = *(const float4*)&bbase[l * NS];
            float4 Cv = *(const float4*)&cbase[l * NS];
            float dxv = delta * xv;
            h0 = fmaf(ex2f(delta * a20), h0, dxv * Bv.x);
            h1 = fmaf(ex2f(delta * a21), h1, dxv * Bv.y);
            h2 = fmaf(ex2f(delta * a22), h2, dxv * Bv.z);
            h3 = fmaf(ex2f(delta * a23), h3, dxv * Bv.w);
            float v = h0 * Cv.x + h1 * Cv.y + h2 * Cv.z + h3 * Cv.w;
            v += __shfl_xor_sync(0xffffffffu, v, 1);
            v += __shfl_xor_sync(0xffffffffu, v, 2);
            if (n4 == 0) yptr[s] = fmaf(Dv, xv, v);
            l++;
            if (K == 0) s++;
            else if (K == 2) s--;
            else if (K == 1) { r56++; s += HW; if (r56 == HW) { r56 = 0; s -= L - 1; } }
            else             { r56++; s -= HW; if (r56 == HW) { r56 = 0; s += L - 1; } }
        }
    }
}

__global__ void k_scanC(const float* __restrict__ alogs, const float* __restrict__ ds) {
    const int k = blockIdx.x / 147;
    const int gl = (blockIdx.x % 147) * 64 + (threadIdx.x >> 2);
    const int n4 = threadIdx.x & 3;
    const int d = gl / NC, c = gl % NC;
    const int kd = k * DI + d;
    switch (k) {
        case 0: scanC_body<0>(kd, d, c, n4, alogs, ds); break;
        case 1: scanC_body<1>(kd, d, c, n4, alogs, ds); break;
        case 2: scanC_body<2>(kd, d, c, n4, alogs, ds); break;
        default: scanC_body<3>(kd, d, c, n4, alogs, ds); break;
    }
}

// ---------------- K5: merge 4 dirs + LayerNorm + z-gate + out_proj --------
__global__ void k_merge_out(const float* __restrict__ lnw, const float* __restrict__ lnb,
                            const float* __restrict__ ow, float* __restrict__ out) {
    __shared__ float yt[DI * 33];
    __shared__ float red1[256], red2[256];
    __shared__ float mu_s[32], rs_s[32];
    const int s0 = blockIdx.x * 32;
    const int tid = threadIdx.x;

    for (int e = tid; e < DI * 32; e += 256) {
        int d = e >> 5, ls = e & 31;
        int s = s0 + ls;
        float v = g_y4[d * L + s] + g_y4[(DI + d) * L + s] +
                  g_y4[(2 * DI + d) * L + s] + g_y4[(3 * DI + d) * L + s];
        yt[d * 33 + ls] = v;
    }
    __syncthreads();
    {
        int j = tid >> 5, ls = tid & 31;
        float s1 = 0.f, s2 = 0.f;
        for (int d = j; d < DI; d += 8) {
            float v = yt[d * 33 + ls];
            s1 += v; s2 += v * v;
        }
        red1[tid] = s1; red2[tid] = s2;
    }
    __syncthreads();
    if (tid < 32) {
        float s1 = 0.f, s2 = 0.f;
        #pragma unroll
        for (int j = 0; j < 8; j++) { s1 += red1[j * 32 + tid]; s2 += red2[j * 32 + tid]; }
        float mu = s1 / DI;
        float var = s2 / DI - mu * mu;
        mu_s[tid] = mu;
        rs_s[tid] = rsqrtf(var + 1e-5f);
    }
    __syncthreads();
    for (int e = tid; e < DI * 32; e += 256) {
        int ls = e / DI, d = e % DI;
        float v = yt[d * 33 + ls];
        v = (v - mu_s[ls]) * rs_s[ls] * lnw[d] + lnb[d];
        v *= g_z[(s0 + ls) * DI + d];
        yt[d * 33 + ls] = v;
    }
    __syncthreads();
    {
        int ls = tid & 31, og = tid >> 5;
        float acc[12] = {};
        for (int d = 0; d < DI; d++) {
            float yv = yt[d * 33 + ls];
            #pragma unroll
            for (int j = 0; j < 12; j++) acc[j] += yv * __ldg(&ow[(og + 8 * j) * DI + d]);
        }
        #pragma unroll
        for (int j = 0; j < 12; j++) out[(s0 + ls) * DM + og + 8 * j] = acc[j];
    }
}

// ---------------- launch ---------------------------------------------------
extern "C" void kernel_launch(void* const* d_in, const int* in_sizes, int n_in,
                              void* d_out, int out_size) {
    const float* x     = (const float*)d_in[0];
    const float* inw   = (const float*)d_in[1];
    const float* cw    = (const float*)d_in[2];
    const float* cb    = (const float*)d_in[3];
    const float* xpw   = (const float*)d_in[4];
    const float* dtw   = (const float*)d_in[5];
    const float* dtb   = (const float*)d_in[6];
    const float* alogs = (const float*)d_in[7];
    const float* ds    = (const float*)d_in[8];
    const float* lnw   = (const float*)d_in[9];
    const float* lnb   = (const float*)d_in[10];
    const float* ow    = (const float*)d_in[11];
    float* out = (float*)d_out;

    k_inproj<<<dim3(98, 6), 256>>>(x, inw);
    k_conv<<<dim3(192, 14), dim3(56, 4)>>>(cw, cb);
    k_xt<<<192, 256>>>();
    k_xdbl<<<dim3(49, 4), 256>>>(xpw);
    k_dx<<<dim3(28, 4), 256>>>(dtw, dtb);
    k_scanA<<<588, 256>>>(alogs);
    k_scanB<<<12, 256>>>();
    k_scanC<<<588, 256>>>(alogs, ds);
    k_merge_out<<<98, 256>>>(lnw, lnb, ow, out);
}

// round 7
// speedup vs baseline: 5.6488x; 1.1603x over previous
#include <cuda_runtime.h>
#include <math.h>

#define L    3136
#define HW   56
#define DM   96
#define DI   192
#define NS   16
#define KDIR 4
#define RR   6
#define NCH  64
#define CL   49

// ---------------- scratch (device globals; no allocation) ----------------
__device__ float g_xc[DI * L];           // conv input, channel-major [d][s]
__device__ float g_z[L * DI];            // gate, pixel-major [s][d]
__device__ float g_xconv[DI * L];        // conv output, channel-major [d][s]
__device__ float g_dts[KDIR * RR * L];   // low-rank dt, scan order [k*6+r][l]
__device__ float g_Bs[KDIR * L * NS];    // scan order [(k*L+l)*16+n]
__device__ float g_Cs[KDIR * L * NS];
__device__ float g_y4[KDIR * DI * L];    // per-direction y at SPATIAL index

__device__ __forceinline__ float siluf(float x) { return x / (1.f + __expf(-x)); }
__device__ __forceinline__ float softplusf(float x) {
    return x > 20.f ? x : __logf(1.f + __expf(x));
}
__device__ __forceinline__ float ex2f(float x) {
    float r;
    asm("ex2.approx.f32 %0, %1;" : "=f"(r) : "f"(x));
    return r;
}
#define LOG2E 1.4426950408889634f

// ---------------- K1: in_proj GEMM (L x 96) @ (96 x 384), split xc/z ------
__global__ void k_inproj(const float* __restrict__ x, const float* __restrict__ w) {
    __shared__ float As[32 * 96];
    __shared__ float Bs[96 * 65];
    __shared__ float Csh[64 * 33];
    const int l0 = blockIdx.x * 32;
    const int o0 = blockIdx.y * 64;
    const int tid = threadIdx.x;

    for (int e = tid; e < 32 * 96; e += 256)
        As[e] = x[(l0 + e / 96) * 96 + (e % 96)];
    for (int e = tid; e < 96 * 64; e += 256) {
        int o = e / 96, c = e % 96;
        Bs[c * 65 + o] = w[(o0 + o) * 96 + c];
    }
    __syncthreads();

    const int tl = tid >> 5, to = tid & 31;
    float acc[4][2] = {};
    #pragma unroll 8
    for (int kk = 0; kk < 96; kk++) {
        float b0 = Bs[kk * 65 + to];
        float b1 = Bs[kk * 65 + to + 32];
        #pragma unroll
        for (int i = 0; i < 4; i++) {
            float a = As[(tl * 4 + i) * 96 + kk];
            acc[i][0] += a * b0;
            acc[i][1] += a * b1;
        }
    }
    __syncthreads();
    #pragma unroll
    for (int i = 0; i < 4; i++) {
        Csh[to * 33 + tl * 4 + i] = acc[i][0];
        Csh[(to + 32) * 33 + tl * 4 + i] = acc[i][1];
    }
    __syncthreads();

    for (int e = tid; e < 2048; e += 256) {
        int ol = e >> 5, l = e & 31;
        int o = o0 + ol;
        if (o < DI) g_xc[o * L + l0 + l] = Csh[ol * 33 + l];
    }
    for (int e = tid; e < 2048; e += 256) {
        int l = e >> 6, ol = e & 63;
        int o = o0 + ol;
        if (o >= DI) {
            float v = Csh[ol * 33 + l];
            g_z[(l0 + l) * DI + (o - DI)] = siluf(v);
        }
    }
}

// ---------------- K2: depthwise 3x3 conv SAME + silu ----------------------
__global__ void k_conv(const float* __restrict__ cw, const float* __restrict__ cb) {
    const int d = blockIdx.x;
    const int h = blockIdx.y * 4 + threadIdx.y;
    const int w = threadIdx.x;
    float wgt[9];
    #pragma unroll
    for (int i = 0; i < 9; i++) wgt[i] = cw[d * 9 + i];
    float acc = cb[d];
    const float* base = g_xc + d * L;
    #pragma unroll
    for (int i = 0; i < 3; i++) {
        int hh = h + i - 1;
        if (hh < 0 || hh >= HW) continue;
        #pragma unroll
        for (int j = 0; j < 3; j++) {
            int ww = w + j - 1;
            if (ww < 0 || ww >= HW) continue;
            acc += base[hh * HW + ww] * wgt[i * 3 + j];
        }
    }
    g_xconv[d * L + h * HW + w] = siluf(acc);
}

// ---------------- K3: x_dbl projection GEMM, scatter into scan order -----
#define XD_KC 96
__global__ void k_xdbl(const float* __restrict__ xpw) {
    __shared__ float ws[40 * XD_KC];    // [row][dd]
    __shared__ float xs[XD_KC * 64];    // [dd][ss]
    const int k = blockIdx.y;
    const int s0 = blockIdx.x * 64;
    const int tid = threadIdx.x;
    const int tx = tid & 31;
    const int ty = tid >> 5;
    const int r0 = ty * 5;

    float acc[5][2];
    #pragma unroll
    for (int j = 0; j < 5; j++) { acc[j][0] = 0.f; acc[j][1] = 0.f; }

    for (int d0 = 0; d0 < DI; d0 += XD_KC) {
        __syncthreads();
        for (int e = tid; e < 40 * XD_KC; e += 256) {
            int row = e / XD_KC, dd = e % XD_KC;
            ws[e] = (row < 38) ? xpw[(k * 38 + row) * DI + d0 + dd] : 0.f;
        }
        #pragma unroll
        for (int e = tid; e < XD_KC * 64; e += 256) {
            int dd = e >> 6, ss = e & 63;
            xs[e] = g_xconv[(d0 + dd) * L + s0 + ss];
        }
        __syncthreads();
        #pragma unroll 4
        for (int dd = 0; dd < XD_KC; dd++) {
            float2 xv = *(const float2*)&xs[dd * 64 + tx * 2];
            #pragma unroll
            for (int j = 0; j < 5; j++) {
                float wv = ws[(r0 + j) * XD_KC + dd];
                acc[j][0] = fmaf(wv, xv.x, acc[j][0]);
                acc[j][1] = fmaf(wv, xv.y, acc[j][1]);
            }
        }
    }

    #pragma unroll
    for (int j = 0; j < 5; j++) {
        int r = r0 + j;
        if (r >= 38) break;
        #pragma unroll
        for (int c = 0; c < 2; c++) {
            int s = s0 + tx * 2 + c;
            int hs = s / HW, wsp = s % HW;
            int tpos = wsp * HW + hs;
            int lp = (k == 0) ? s : (k == 1) ? tpos : (k == 2) ? (L - 1 - s) : (L - 1 - tpos);
            float v = acc[j][c];
            if (r < RR)            g_dts[(k * RR + r) * L + lp] = v;
            else if (r < RR + NS)  g_Bs[(k * L + lp) * NS + (r - RR)] = v;
            else                   g_Cs[(k * L + lp) * NS + (r - RR - NS)] = v;
        }
    }
}

// ---------------- K4: fused scan (delta, x staging + A + carry + C) -------
// One block per kd. 256 threads = 64 groups x 4 lanes, chunk = 49 steps.
template<int K>
__device__ __forceinline__ void scan_body(
    int kd, int d,
    const float* __restrict__ alogs, const float* __restrict__ ds,
    const float* __restrict__ dtw, const float* __restrict__ dtb,
    float* __restrict__ sx, float* __restrict__ sdelta,
    float* __restrict__ sP, float* __restrict__ sH)
{
    const int tid = threadIdx.x;

    // ---- phase 0a: stage x in scan order (transpose in smem for K=1/3) ----
    const float* __restrict__ xsrc = g_xconv + d * L;
    if (K == 0) {
        for (int e = tid; e < L; e += 256) sx[e] = xsrc[e];
    } else if (K == 2) {
        for (int e = tid; e < L; e += 256) sx[L - 1 - e] = xsrc[e];
    } else if (K == 1) {
        for (int e = tid; e < L; e += 256) {
            int h = e / HW, w = e % HW;
            sx[w * HW + h] = xsrc[e];
        }
    } else {
        for (int e = tid; e < L; e += 256) {
            int h = e / HW, w = e % HW;
            sx[L - 1 - (w * HW + h)] = xsrc[e];
        }
    }

    // ---- phase 0b: delta = softplus(dts . w + b) ----
    float wr[6];
    #pragma unroll
    for (int r = 0; r < 6; r++) wr[r] = dtw[kd * 6 + r];
    const float b = dtb[kd];
    const float* __restrict__ dbase = g_dts + K * RR * L;
    for (int e = tid; e < L; e += 256) {
        float a = b;
        #pragma unroll
        for (int r = 0; r < 6; r++) a = fmaf(dbase[r * L + e], wr[r], a);
        sdelta[e] = softplusf(a);
    }
    __syncthreads();

    // ---- phase A: per-chunk scan ----
    const int g = tid >> 2, n4 = tid & 3;
    float4 al = *(const float4*)&alogs[kd * NS + n4 * 4];
    const float a20 = -__expf(al.x) * LOG2E;
    const float a21 = -__expf(al.y) * LOG2E;
    const float a22 = -__expf(al.z) * LOG2E;
    const float a23 = -__expf(al.w) * LOG2E;
    const float* __restrict__ bbase = g_Bs + K * L * NS + n4 * 4;
    const int l0 = g * CL;

    float h0 = 0.f, h1 = 0.f, h2 = 0.f, h3 = 0.f, sd = 0.f;
    {
        int l = l0;
        #pragma unroll 7
        for (int i = 0; i < CL; i++, l++) {
            float delta = sdelta[l];
            float xv = sx[l];
            float4 Bv = *(const float4*)&bbase[l * NS];
            float dxv = delta * xv;
            h0 = fmaf(ex2f(delta * a20), h0, dxv * Bv.x);
            h1 = fmaf(ex2f(delta * a21), h1, dxv * Bv.y);
            h2 = fmaf(ex2f(delta * a22), h2, dxv * Bv.z);
            h3 = fmaf(ex2f(delta * a23), h3, dxv * Bv.w);
            sd += delta;
        }
    }
    float4 P, H;
    P.x = ex2f(a20 * sd); P.y = ex2f(a21 * sd);
    P.z = ex2f(a22 * sd); P.w = ex2f(a23 * sd);
    H.x = h0; H.y = h1; H.z = h2; H.w = h3;
    *(float4*)&sP[tid * 4] = P;   // tid*4 == g*16 + n4*4
    *(float4*)&sH[tid * 4] = H;
    __syncthreads();

    // ---- phase B: Kogge-Stone inclusive scan over 64 chunks ----
    #pragma unroll
    for (int off = 1; off < NCH; off <<= 1) {
        float4 Pp, Hp;
        const bool valid = (g >= off);
        if (valid) {
            Pp = *(const float4*)&sP[(tid - off * 4) * 4];
            Hp = *(const float4*)&sH[(tid - off * 4) * 4];
        }
        __syncthreads();
        if (valid) {
            H.x = fmaf(P.x, Hp.x, H.x); P.x *= Pp.x;
            H.y = fmaf(P.y, Hp.y, H.y); P.y *= Pp.y;
            H.z = fmaf(P.z, Hp.z, H.z); P.z *= Pp.z;
            H.w = fmaf(P.w, Hp.w, H.w); P.w *= Pp.w;
            *(float4*)&sP[tid * 4] = P;
            *(float4*)&sH[tid * 4] = H;
        }
        __syncthreads();
    }

    float4 Hin = {0.f, 0.f, 0.f, 0.f};
    if (g > 0) Hin = *(const float4*)&sH[(tid - 4) * 4];

    // ---- phase C: replay chunk with h_in, emit y ----
    const float Dv = ds[kd];
    const float* __restrict__ cbase = g_Cs + K * L * NS + n4 * 4;
    float* __restrict__ yptr = g_y4 + kd * L;
    h0 = Hin.x; h1 = Hin.y; h2 = Hin.z; h3 = Hin.w;

    int l = l0;
    int r56 = l0 % HW;
    int s;
    if (K == 0) s = l0;
    else if (K == 1) s = r56 * HW + l0 / HW;
    else if (K == 2) s = L - 1 - l0;
    else s = L - 1 - (r56 * HW + l0 / HW);

    #pragma unroll 7
    for (int i = 0; i < CL; i++) {
        float delta = sdelta[l];
        float xv = sx[l];
        float4 Bv = *(const float4*)&bbase[l * NS];
        float4 Cv = *(const float4*)&cbase[l * NS];
        float dxv = delta * xv;
        h0 = fmaf(ex2f(delta * a20), h0, dxv * Bv.x);
        h1 = fmaf(ex2f(delta * a21), h1, dxv * Bv.y);
        h2 = fmaf(ex2f(delta * a22), h2, dxv * Bv.z);
        h3 = fmaf(ex2f(delta * a23), h3, dxv * Bv.w);
        float v = h0 * Cv.x + h1 * Cv.y + h2 * Cv.z + h3 * Cv.w;
        v += __shfl_xor_sync(0xffffffffu, v, 1);
        v += __shfl_xor_sync(0xffffffffu, v, 2);
        if (n4 == 0) yptr[s] = fmaf(Dv, xv, v);
        l++;
        if (K == 0) s++;
        else if (K == 2) s--;
        else if (K == 1) { r56++; s += HW; if (r56 == HW) { r56 = 0; s -= L - 1; } }
        else             { r56++; s -= HW; if (r56 == HW) { r56 = 0; s += L - 1; } }
    }
}

__global__ void k_scan(const float* __restrict__ alogs, const float* __restrict__ ds,
                       const float* __restrict__ dtw, const float* __restrict__ dtb) {
    __shared__ float sx[L];
    __shared__ float sdelta[L];
    __shared__ float sP[NCH * NS];
    __shared__ float sH[NCH * NS];
    const int kd = blockIdx.x;
    const int k = kd / DI, d = kd % DI;
    switch (k) {
        case 0: scan_body<0>(kd, d, alogs, ds, dtw, dtb, sx, sdelta, sP, sH); break;
        case 1: scan_body<1>(kd, d, alogs, ds, dtw, dtb, sx, sdelta, sP, sH); break;
        case 2: scan_body<2>(kd, d, alogs, ds, dtw, dtb, sx, sdelta, sP, sH); break;
        default: scan_body<3>(kd, d, alogs, ds, dtw, dtb, sx, sdelta, sP, sH); break;
    }
}

// ---------------- K5: merge 4 dirs + LayerNorm + z-gate + out_proj --------
__global__ void k_merge_out(const float* __restrict__ lnw, const float* __restrict__ lnb,
                            const float* __restrict__ ow, float* __restrict__ out) {
    __shared__ float yt[DI * 33];
    __shared__ float red1[256], red2[256];
    __shared__ float mu_s[32], rs_s[32];
    const int s0 = blockIdx.x * 32;
    const int tid = threadIdx.x;

    for (int e = tid; e < DI * 32; e += 256) {
        int d = e >> 5, ls = e & 31;
        int s = s0 + ls;
        float v = g_y4[d * L + s] + g_y4[(DI + d) * L + s] +
                  g_y4[(2 * DI + d) * L + s] + g_y4[(3 * DI + d) * L + s];
        yt[d * 33 + ls] = v;
    }
    __syncthreads();
    {
        int j = tid >> 5, ls = tid & 31;
        float s1 = 0.f, s2 = 0.f;
        for (int d = j; d < DI; d += 8) {
            float v = yt[d * 33 + ls];
            s1 += v; s2 += v * v;
        }
        red1[tid] = s1; red2[tid] = s2;
    }
    __syncthreads();
    if (tid < 32) {
        float s1 = 0.f, s2 = 0.f;
        #pragma unroll
        for (int j = 0; j < 8; j++) { s1 += red1[j * 32 + tid]; s2 += red2[j * 32 + tid]; }
        float mu = s1 / DI;
        float var = s2 / DI - mu * mu;
        mu_s[tid] = mu;
        rs_s[tid] = rsqrtf(var + 1e-5f);
    }
    __syncthreads();
    for (int e = tid; e < DI * 32; e += 256) {
        int ls = e / DI, d = e % DI;
        float v = yt[d * 33 + ls];
        v = (v - mu_s[ls]) * rs_s[ls] * lnw[d] + lnb[d];
        v *= g_z[(s0 + ls) * DI + d];
        yt[d * 33 + ls] = v;
    }
    __syncthreads();
    {
        int ls = tid & 31, og = tid >> 5;
        float acc[12] = {};
        for (int d = 0; d < DI; d++) {
            float yv = yt[d * 33 + ls];
            #pragma unroll
            for (int j = 0; j < 12; j++) acc[j] += yv * __ldg(&ow[(og + 8 * j) * DI + d]);
        }
        #pragma unroll
        for (int j = 0; j < 12; j++) out[(s0 + ls) * DM + og + 8 * j] = acc[j];
    }
}

// ---------------- launch ---------------------------------------------------
extern "C" void kernel_launch(void* const* d_in, const int* in_sizes, int n_in,
                              void* d_out, int out_size) {
    const float* x     = (const float*)d_in[0];
    const float* inw   = (const float*)d_in[1];
    const float* cw    = (const float*)d_in[2];
    const float* cb    = (const float*)d_in[3];
    const float* xpw   = (const float*)d_in[4];
    const float* dtw   = (const float*)d_in[5];
    const float* dtb   = (const float*)d_in[6];
    const float* alogs = (const float*)d_in[7];
    const float* ds    = (const float*)d_in[8];
    const float* lnw   = (const float*)d_in[9];
    const float* lnb   = (const float*)d_in[10];
    const float* ow    = (const float*)d_in[11];
    float* out = (float*)d_out;

    k_inproj<<<dim3(98, 6), 256>>>(x, inw);
    k_conv<<<dim3(192, 14), dim3(56, 4)>>>(cw, cb);
    k_xdbl<<<dim3(49, 4), 256>>>(xpw);
    k_scan<<<768, 256>>>(alogs, ds, dtw, dtb);
    k_merge_out<<<98, 256>>>(lnw, lnb, ow, out);
}

// round 8
// speedup vs baseline: 7.2710x; 1.2872x over previous
#include <cuda_runtime.h>
#include <math.h>

#define L    3136
#define HW   56
#define DM   96
#define DI   192
#define NS   16
#define KDIR 4
#define RR   6
#define NCH  64
#define CL   49

// ---------------- scratch (device globals; no allocation) ----------------
__device__ float g_xc[DI * L];           // conv input, channel-major [d][s]
__device__ float g_z[L * DI];            // gate, pixel-major [s][d]
__device__ float g_xconv[DI * L];        // conv output, channel-major [d][s]
__device__ float g_dts[KDIR * RR * L];   // low-rank dt, scan order [k*6+r][l]
// B/C in CHUNK-INTERLEAVED scan order: index (i*64+c)*16+n where l = c*49+i
__device__ float g_Bs[KDIR * L * NS];
__device__ float g_Cs[KDIR * L * NS];
__device__ float g_y4[KDIR * DI * L];    // per-direction y at SPATIAL index

__device__ __forceinline__ float siluf(float x) { return x / (1.f + __expf(-x)); }
__device__ __forceinline__ float softplusf(float x) {
    return x > 20.f ? x : __logf(1.f + __expf(x));
}
__device__ __forceinline__ float ex2f(float x) {
    float r;
    asm("ex2.approx.f32 %0, %1;" : "=f"(r) : "f"(x));
    return r;
}
#define LOG2E 1.4426950408889634f

// ---------------- K1: in_proj GEMM (L x 96) @ (96 x 384), split xc/z ------
__global__ void k_inproj(const float* __restrict__ x, const float* __restrict__ w) {
    __shared__ float As[32 * 96];
    __shared__ float Bs[96 * 65];
    __shared__ float Csh[64 * 33];
    const int l0 = blockIdx.x * 32;
    const int o0 = blockIdx.y * 64;
    const int tid = threadIdx.x;

    for (int e = tid; e < 32 * 96; e += 256)
        As[e] = x[(l0 + e / 96) * 96 + (e % 96)];
    for (int e = tid; e < 96 * 64; e += 256) {
        int o = e / 96, c = e % 96;
        Bs[c * 65 + o] = w[(o0 + o) * 96 + c];
    }
    __syncthreads();

    const int tl = tid >> 5, to = tid & 31;
    float acc[4][2] = {};
    #pragma unroll 8
    for (int kk = 0; kk < 96; kk++) {
        float b0 = Bs[kk * 65 + to];
        float b1 = Bs[kk * 65 + to + 32];
        #pragma unroll
        for (int i = 0; i < 4; i++) {
            float a = As[(tl * 4 + i) * 96 + kk];
            acc[i][0] += a * b0;
            acc[i][1] += a * b1;
        }
    }
    __syncthreads();
    #pragma unroll
    for (int i = 0; i < 4; i++) {
        Csh[to * 33 + tl * 4 + i] = acc[i][0];
        Csh[(to + 32) * 33 + tl * 4 + i] = acc[i][1];
    }
    __syncthreads();

    for (int e = tid; e < 2048; e += 256) {
        int ol = e >> 5, l = e & 31;
        int o = o0 + ol;
        if (o < DI) g_xc[o * L + l0 + l] = Csh[ol * 33 + l];
    }
    for (int e = tid; e < 2048; e += 256) {
        int l = e >> 6, ol = e & 63;
        int o = o0 + ol;
        if (o >= DI) {
            float v = Csh[ol * 33 + l];
            g_z[(l0 + l) * DI + (o - DI)] = siluf(v);
        }
    }
}

// ---------------- K2: depthwise 3x3 conv SAME + silu ----------------------
__global__ void k_conv(const float* __restrict__ cw, const float* __restrict__ cb) {
    const int d = blockIdx.x;
    const int h = blockIdx.y * 4 + threadIdx.y;
    const int w = threadIdx.x;
    float wgt[9];
    #pragma unroll
    for (int i = 0; i < 9; i++) wgt[i] = cw[d * 9 + i];
    float acc = cb[d];
    const float* base = g_xc + d * L;
    #pragma unroll
    for (int i = 0; i < 3; i++) {
        int hh = h + i - 1;
        if (hh < 0 || hh >= HW) continue;
        #pragma unroll
        for (int j = 0; j < 3; j++) {
            int ww = w + j - 1;
            if (ww < 0 || ww >= HW) continue;
            acc += base[hh * HW + ww] * wgt[i * 3 + j];
        }
    }
    g_xconv[d * L + h * HW + w] = siluf(acc);
}

// ---------------- K3: x_dbl projection GEMM, scatter into scan order -----
#define XD_KC 96
__global__ void k_xdbl(const float* __restrict__ xpw) {
    __shared__ float ws[40 * XD_KC];    // [row][dd]
    __shared__ float xs[XD_KC * 64];    // [dd][ss]
    const int k = blockIdx.y;
    const int s0 = blockIdx.x * 64;
    const int tid = threadIdx.x;
    const int tx = tid & 31;
    const int ty = tid >> 5;
    const int r0 = ty * 5;

    float acc[5][2];
    #pragma unroll
    for (int j = 0; j < 5; j++) { acc[j][0] = 0.f; acc[j][1] = 0.f; }

    for (int d0 = 0; d0 < DI; d0 += XD_KC) {
        __syncthreads();
        for (int e = tid; e < 40 * XD_KC; e += 256) {
            int row = e / XD_KC, dd = e % XD_KC;
            ws[e] = (row < 38) ? xpw[(k * 38 + row) * DI + d0 + dd] : 0.f;
        }
        #pragma unroll
        for (int e = tid; e < XD_KC * 64; e += 256) {
            int dd = e >> 6, ss = e & 63;
            xs[e] = g_xconv[(d0 + dd) * L + s0 + ss];
        }
        __syncthreads();
        #pragma unroll 4
        for (int dd = 0; dd < XD_KC; dd++) {
            float2 xv = *(const float2*)&xs[dd * 64 + tx * 2];
            #pragma unroll
            for (int j = 0; j < 5; j++) {
                float wv = ws[(r0 + j) * XD_KC + dd];
                acc[j][0] = fmaf(wv, xv.x, acc[j][0]);
                acc[j][1] = fmaf(wv, xv.y, acc[j][1]);
            }
        }
    }

    #pragma unroll
    for (int j = 0; j < 5; j++) {
        int r = r0 + j;
        if (r >= 38) break;
        #pragma unroll
        for (int c = 0; c < 2; c++) {
            int s = s0 + tx * 2 + c;
            int hs = s / HW, wsp = s % HW;
            int tpos = wsp * HW + hs;
            int lp = (k == 0) ? s : (k == 1) ? tpos : (k == 2) ? (L - 1 - s) : (L - 1 - tpos);
            float v = acc[j][c];
            if (r < RR) {
                g_dts[(k * RR + r) * L + lp] = v;
            } else {
                int cc = lp / CL, ii = lp - cc * CL;
                int pos = k * L * NS + (ii * NCH + cc) * NS;
                if (r < RR + NS) g_Bs[pos + (r - RR)] = v;
                else             g_Cs[pos + (r - RR - NS)] = v;
            }
        }
    }
}

// ---------------- K4: fused scan -------------------------------------------
// One block per kd. 256 threads = 64 groups x 4 lanes, chunk = 49 steps.
template<int K>
__device__ __forceinline__ void scan_body(
    int kd, int d,
    const float* __restrict__ alogs, const float* __restrict__ ds,
    const float* __restrict__ dtw, const float* __restrict__ dtb,
    float* __restrict__ sx, float* __restrict__ sdelta, float* __restrict__ sy,
    float* __restrict__ sP, float* __restrict__ sH)
{
    const int tid = threadIdx.x;

    // ---- phase 0a: stage x in scan order (transpose in smem for K=1/3) ----
    const float* __restrict__ xsrc = g_xconv + d * L;
    if (K == 0) {
        for (int e = tid; e < L; e += 256) sx[e] = xsrc[e];
    } else if (K == 2) {
        for (int e = tid; e < L; e += 256) sx[L - 1 - e] = xsrc[e];
    } else if (K == 1) {
        for (int e = tid; e < L; e += 256) {
            int h = e / HW, w = e % HW;
            sx[w * HW + h] = xsrc[e];
        }
    } else {
        for (int e = tid; e < L; e += 256) {
            int h = e / HW, w = e % HW;
            sx[L - 1 - (w * HW + h)] = xsrc[e];
        }
    }

    // ---- phase 0b: delta = softplus(dts . w + b) ----
    float wr[6];
    #pragma unroll
    for (int r = 0; r < 6; r++) wr[r] = dtw[kd * 6 + r];
    const float b = dtb[kd];
    const float* __restrict__ dbase = g_dts + K * RR * L;
    for (int e = tid; e < L; e += 256) {
        float a = b;
        #pragma unroll
        for (int r = 0; r < 6; r++) a = fmaf(dbase[r * L + e], wr[r], a);
        sdelta[e] = softplusf(a);
    }
    __syncthreads();

    // ---- phase A: per-chunk scan ----
    const int g = tid >> 2, n4 = tid & 3;
    float4 al = *(const float4*)&alogs[kd * NS + n4 * 4];
    const float a20 = -__expf(al.x) * LOG2E;
    const float a21 = -__expf(al.y) * LOG2E;
    const float a22 = -__expf(al.z) * LOG2E;
    const float a23 = -__expf(al.w) * LOG2E;
    const float* __restrict__ bbase = g_Bs + K * L * NS + n4 * 4;
    const int l0 = g * CL;

    float h0 = 0.f, h1 = 0.f, h2 = 0.f, h3 = 0.f, sd = 0.f;
    {
        int l = l0;
        int m = g * NS;                  // (i*64+g)*16, i=0
        #pragma unroll 7
        for (int i = 0; i < CL; i++, l++, m += NCH * NS) {
            float delta = sdelta[l];
            float xv = sx[l];
            float4 Bv = *(const float4*)&bbase[m];
            float dxv = delta * xv;
            h0 = fmaf(ex2f(delta * a20), h0, dxv * Bv.x);
            h1 = fmaf(ex2f(delta * a21), h1, dxv * Bv.y);
            h2 = fmaf(ex2f(delta * a22), h2, dxv * Bv.z);
            h3 = fmaf(ex2f(delta * a23), h3, dxv * Bv.w);
            sd += delta;
        }
    }
    float4 P, H;
    P.x = ex2f(a20 * sd); P.y = ex2f(a21 * sd);
    P.z = ex2f(a22 * sd); P.w = ex2f(a23 * sd);
    H.x = h0; H.y = h1; H.z = h2; H.w = h3;
    *(float4*)&sP[tid * 4] = P;
    *(float4*)&sH[tid * 4] = H;
    __syncthreads();

    // ---- phase B: Kogge-Stone inclusive scan over 64 chunks ----
    #pragma unroll
    for (int off = 1; off < NCH; off <<= 1) {
        float4 Pp, Hp;
        const bool valid = (g >= off);
        if (valid) {
            Pp = *(const float4*)&sP[(tid - off * 4) * 4];
            Hp = *(const float4*)&sH[(tid - off * 4) * 4];
        }
        __syncthreads();
        if (valid) {
            H.x = fmaf(P.x, Hp.x, H.x); P.x *= Pp.x;
            H.y = fmaf(P.y, Hp.y, H.y); P.y *= Pp.y;
            H.z = fmaf(P.z, Hp.z, H.z); P.z *= Pp.z;
            H.w = fmaf(P.w, Hp.w, H.w); P.w *= Pp.w;
            *(float4*)&sP[tid * 4] = P;
            *(float4*)&sH[tid * 4] = H;
        }
        __syncthreads();
    }

    float4 Hin = {0.f, 0.f, 0.f, 0.f};
    if (g > 0) Hin = *(const float4*)&sH[(tid - 4) * 4];

    // ---- phase C: replay chunk with h_in, write y to smem ----
    const float Dv = ds[kd];
    const float* __restrict__ cbase = g_Cs + K * L * NS + n4 * 4;
    h0 = Hin.x; h1 = Hin.y; h2 = Hin.z; h3 = Hin.w;

    {
        int l = l0;
        int m = g * NS;
        #pragma unroll 7
        for (int i = 0; i < CL; i++, l++, m += NCH * NS) {
            float delta = sdelta[l];
            float xv = sx[l];
            float4 Bv = *(const float4*)&bbase[m];
            float4 Cv = *(const float4*)&cbase[m];
            float dxv = delta * xv;
            h0 = fmaf(ex2f(delta * a20), h0, dxv * Bv.x);
            h1 = fmaf(ex2f(delta * a21), h1, dxv * Bv.y);
            h2 = fmaf(ex2f(delta * a22), h2, dxv * Bv.z);
            h3 = fmaf(ex2f(delta * a23), h3, dxv * Bv.w);
            float v = h0 * Cv.x + h1 * Cv.y + h2 * Cv.z + h3 * Cv.w;
            v += __shfl_xor_sync(0xffffffffu, v, 1);
            v += __shfl_xor_sync(0xffffffffu, v, 2);
            if (n4 == 0) sy[l] = fmaf(Dv, xv, v);
        }
    }
    __syncthreads();

    // ---- epilogue: write y coalesced at spatial index ----
    float* __restrict__ yptr = g_y4 + kd * L;
    if (K == 0) {
        for (int e = tid; e < L; e += 256) yptr[e] = sy[e];
    } else if (K == 2) {
        for (int e = tid; e < L; e += 256) yptr[e] = sy[L - 1 - e];
    } else if (K == 1) {
        for (int e = tid; e < L; e += 256) {
            int h = e / HW, w = e % HW;
            yptr[e] = sy[w * HW + h];
        }
    } else {
        for (int e = tid; e < L; e += 256) {
            int m = L - 1 - e;
            int h = m / HW, w = m % HW;
            yptr[e] = sy[w * HW + h];
        }
    }
}

__global__ void __launch_bounds__(256) k_scan(
        const float* __restrict__ alogs, const float* __restrict__ ds,
        const float* __restrict__ dtw, const float* __restrict__ dtb) {
    __shared__ float sx[L];
    __shared__ float sdelta[L];
    __shared__ float sy[L];
    __shared__ float sP[NCH * NS];
    __shared__ float sH[NCH * NS];
    const int kd = blockIdx.x;
    const int k = kd / DI, d = kd % DI;
    switch (k) {
        case 0: scan_body<0>(kd, d, alogs, ds, dtw, dtb, sx, sdelta, sy, sP, sH); break;
        case 1: scan_body<1>(kd, d, alogs, ds, dtw, dtb, sx, sdelta, sy, sP, sH); break;
        case 2: scan_body<2>(kd, d, alogs, ds, dtw, dtb, sx, sdelta, sy, sP, sH); break;
        default: scan_body<3>(kd, d, alogs, ds, dtw, dtb, sx, sdelta, sy, sP, sH); break;
    }
}

// ---------------- K5: merge 4 dirs + LayerNorm + z-gate + out_proj --------
__global__ void k_merge_out(const float* __restrict__ lnw, const float* __restrict__ lnb,
                            const float* __restrict__ ow, float* __restrict__ out) {
    __shared__ float yt[DI * 33];
    __shared__ float red1[256], red2[256];
    __shared__ float mu_s[32], rs_s[32];
    const int s0 = blockIdx.x * 32;
    const int tid = threadIdx.x;

    for (int e = tid; e < DI * 32; e += 256) {
        int d = e >> 5, ls = e & 31;
        int s = s0 + ls;
        float v = g_y4[d * L + s] + g_y4[(DI + d) * L + s] +
                  g_y4[(2 * DI + d) * L + s] + g_y4[(3 * DI + d) * L + s];
        yt[d * 33 + ls] = v;
    }
    __syncthreads();
    {
        int j = tid >> 5, ls = tid & 31;
        float s1 = 0.f, s2 = 0.f;
        for (int d = j; d < DI; d += 8) {
            float v = yt[d * 33 + ls];
            s1 += v; s2 += v * v;
        }
        red1[tid] = s1; red2[tid] = s2;
    }
    __syncthreads();
    if (tid < 32) {
        float s1 = 0.f, s2 = 0.f;
        #pragma unroll
        for (int j = 0; j < 8; j++) { s1 += red1[j * 32 + tid]; s2 += red2[j * 32 + tid]; }
        float mu = s1 / DI;
        float var = s2 / DI - mu * mu;
        mu_s[tid] = mu;
        rs_s[tid] = rsqrtf(var + 1e-5f);
    }
    __syncthreads();
    for (int e = tid; e < DI * 32; e += 256) {
        int ls = e / DI, d = e % DI;
        float v = yt[d * 33 + ls];
        v = (v - mu_s[ls]) * rs_s[ls] * lnw[d] + lnb[d];
        v *= g_z[(s0 + ls) * DI + d];
        yt[d * 33 + ls] = v;
    }
    __syncthreads();
    {
        int ls = tid & 31, og = tid >> 5;
        float acc[12] = {};
        for (int d = 0; d < DI; d++) {
            float yv = yt[d * 33 + ls];
            #pragma unroll
            for (int j = 0; j < 12; j++) acc[j] += yv * __ldg(&ow[(og + 8 * j) * DI + d]);
        }
        #pragma unroll
        for (int j = 0; j < 12; j++) out[(s0 + ls) * DM + og + 8 * j] = acc[j];
    }
}

// ---------------- launch ---------------------------------------------------
extern "C" void kernel_launch(void* const* d_in, const int* in_sizes, int n_in,
                              void* d_out, int out_size) {
    const float* x     = (const float*)d_in[0];
    const float* inw   = (const float*)d_in[1];
    const float* cw    = (const float*)d_in[2];
    const float* cb    = (const float*)d_in[3];
    const float* xpw   = (const float*)d_in[4];
    const float* dtw   = (const float*)d_in[5];
    const float* dtb   = (const float*)d_in[6];
    const float* alogs = (const float*)d_in[7];
    const float* ds    = (const float*)d_in[8];
    const float* lnw   = (const float*)d_in[9];
    const float* lnb   = (const float*)d_in[10];
    const float* ow    = (const float*)d_in[11];
    float* out = (float*)d_out;

    k_inproj<<<dim3(98, 6), 256>>>(x, inw);
    k_conv<<<dim3(192, 14), dim3(56, 4)>>>(cw, cb);
    k_xdbl<<<dim3(49, 4), 256>>>(xpw);
    k_scan<<<768, 256>>>(alogs, ds, dtw, dtb);
    k_merge_out<<<98, 256>>>(lnw, lnb, ow, out);
}

// round 9
// speedup vs baseline: 7.5295x; 1.0356x over previous
#include <cuda_runtime.h>
#include <math.h>

#define L    3136
#define HW   56
#define DM   96
#define DI   192
#define NS   16
#define KDIR 4
#define RR   6
#define NCH  64
#define CL   49

// ---------------- scratch (device globals; no allocation) ----------------
__device__ float g_xc[DI * L];           // conv input, channel-major [d][s]
__device__ float g_z[L * DI];            // gate, pixel-major [s][d]
__device__ float g_xconv[DI * L];        // conv output, channel-major [d][s]
__device__ float g_dts[KDIR * RR * L];   // low-rank dt, scan order [k*6+r][l]
// B/C in CHUNK-INTERLEAVED scan order: index (i*64+c)*16+n where l = c*49+i
__device__ float g_Bs[KDIR * L * NS];
__device__ float g_Cs[KDIR * L * NS];
__device__ float g_y4[KDIR * DI * L];    // per-direction y at SPATIAL index

__device__ __forceinline__ float siluf(float x) { return x / (1.f + __expf(-x)); }
__device__ __forceinline__ float softplusf(float x) {
    return x > 20.f ? x : __logf(1.f + __expf(x));
}
__device__ __forceinline__ float ex2f(float x) {
    float r;
    asm("ex2.approx.f32 %0, %1;" : "=f"(r) : "f"(x));
    return r;
}
#define LOG2E 1.4426950408889634f

// ---------------- K1: in_proj GEMM (L x 96) @ (96 x 384), split xc/z ------
__global__ void k_inproj(const float* __restrict__ x, const float* __restrict__ w) {
    __shared__ float As[32 * 96];
    __shared__ float Bs[96 * 65];
    __shared__ float Csh[64 * 33];
    const int l0 = blockIdx.x * 32;
    const int o0 = blockIdx.y * 64;
    const int tid = threadIdx.x;

    for (int e = tid; e < 32 * 96; e += 256)
        As[e] = x[(l0 + e / 96) * 96 + (e % 96)];
    for (int e = tid; e < 96 * 64; e += 256) {
        int o = e / 96, c = e % 96;
        Bs[c * 65 + o] = w[(o0 + o) * 96 + c];
    }
    __syncthreads();

    const int tl = tid >> 5, to = tid & 31;
    float acc[4][2] = {};
    #pragma unroll 8
    for (int kk = 0; kk < 96; kk++) {
        float b0 = Bs[kk * 65 + to];
        float b1 = Bs[kk * 65 + to + 32];
        #pragma unroll
        for (int i = 0; i < 4; i++) {
            float a = As[(tl * 4 + i) * 96 + kk];
            acc[i][0] += a * b0;
            acc[i][1] += a * b1;
        }
    }
    __syncthreads();
    #pragma unroll
    for (int i = 0; i < 4; i++) {
        Csh[to * 33 + tl * 4 + i] = acc[i][0];
        Csh[(to + 32) * 33 + tl * 4 + i] = acc[i][1];
    }
    __syncthreads();

    for (int e = tid; e < 2048; e += 256) {
        int ol = e >> 5, l = e & 31;
        int o = o0 + ol;
        if (o < DI) g_xc[o * L + l0 + l] = Csh[ol * 33 + l];
    }
    for (int e = tid; e < 2048; e += 256) {
        int l = e >> 6, ol = e & 63;
        int o = o0 + ol;
        if (o >= DI) {
            float v = Csh[ol * 33 + l];
            g_z[(l0 + l) * DI + (o - DI)] = siluf(v);
        }
    }
}

// ---------------- K2: depthwise 3x3 conv SAME + silu ----------------------
__global__ void k_conv(const float* __restrict__ cw, const float* __restrict__ cb) {
    const int d = blockIdx.x;
    const int h = blockIdx.y * 4 + threadIdx.y;
    const int w = threadIdx.x;
    float wgt[9];
    #pragma unroll
    for (int i = 0; i < 9; i++) wgt[i] = cw[d * 9 + i];
    float acc = cb[d];
    const float* base = g_xc + d * L;
    #pragma unroll
    for (int i = 0; i < 3; i++) {
        int hh = h + i - 1;
        if (hh < 0 || hh >= HW) continue;
        #pragma unroll
        for (int j = 0; j < 3; j++) {
            int ww = w + j - 1;
            if (ww < 0 || ww >= HW) continue;
            acc += base[hh * HW + ww] * wgt[i * 3 + j];
        }
    }
    g_xconv[d * L + h * HW + w] = siluf(acc);
}

// ---------------- K3: x_dbl projection GEMM, scatter into scan order -----
// grid (98, 4): 32-px tiles x 4 directions. 256 thr: tx=px, ty=5-row group.
#define XD_KC 96
__global__ void k_xdbl(const float* __restrict__ xpw) {
    __shared__ float ws[40 * XD_KC];    // [row][dd]
    __shared__ float xs[XD_KC * 32];    // [dd][ss]
    const int k = blockIdx.y;
    const int s0 = blockIdx.x * 32;
    const int tid = threadIdx.x;
    const int tx = tid & 31;
    const int ty = tid >> 5;
    const int r0 = ty * 5;

    float acc[5] = {};

    for (int d0 = 0; d0 < DI; d0 += XD_KC) {
        __syncthreads();
        for (int e = tid; e < 40 * XD_KC; e += 256) {
            int row = e / XD_KC, dd = e % XD_KC;
            ws[e] = (row < 38) ? xpw[(k * 38 + row) * DI + d0 + dd] : 0.f;
        }
        #pragma unroll
        for (int e = tid; e < XD_KC * 32; e += 256) {
            int dd = e >> 5, ss = e & 31;
            xs[e] = g_xconv[(d0 + dd) * L + s0 + ss];
        }
        __syncthreads();
        #pragma unroll 8
        for (int dd = 0; dd < XD_KC; dd++) {
            float xv = xs[dd * 32 + tx];
            #pragma unroll
            for (int j = 0; j < 5; j++)
                acc[j] = fmaf(ws[(r0 + j) * XD_KC + dd], xv, acc[j]);
        }
    }

    #pragma unroll
    for (int j = 0; j < 5; j++) {
        int r = r0 + j;
        if (r >= 38) break;
        int s = s0 + tx;
        int hs = s / HW, wsp = s % HW;
        int tpos = wsp * HW + hs;
        int lp = (k == 0) ? s : (k == 1) ? tpos : (k == 2) ? (L - 1 - s) : (L - 1 - tpos);
        float v = acc[j];
        if (r < RR) {
            g_dts[(k * RR + r) * L + lp] = v;
        } else {
            int cc = lp / CL, ii = lp - cc * CL;
            int pos = k * L * NS + (ii * NCH + cc) * NS;
            if (r < RR + NS) g_Bs[pos + (r - RR)] = v;
            else             g_Cs[pos + (r - RR - NS)] = v;
        }
    }
}

// ---------------- K4: fused scan -------------------------------------------
// One block per kd. 256 threads = 64 groups x 4 lanes, chunk = 49 steps.
template<int K>
__device__ __forceinline__ void scan_body(
    int kd, int d,
    const float* __restrict__ alogs, const float* __restrict__ ds,
    const float* __restrict__ dtw, const float* __restrict__ dtb,
    float2* __restrict__ sdx, float* __restrict__ sy,
    float* __restrict__ sP, float* __restrict__ sH)
{
    const int tid = threadIdx.x;

    // ---- phase 0a: stage x in scan order (transpose in smem for K=1/3) ----
    const float* __restrict__ xsrc = g_xconv + d * L;
    if (K == 0) {
        for (int e = tid; e < L; e += 256) sdx[e].y = xsrc[e];
    } else if (K == 2) {
        for (int e = tid; e < L; e += 256) sdx[L - 1 - e].y = xsrc[e];
    } else if (K == 1) {
        for (int e = tid; e < L; e += 256) {
            int h = e / HW, w = e % HW;
            sdx[w * HW + h].y = xsrc[e];
        }
    } else {
        for (int e = tid; e < L; e += 256) {
            int h = e / HW, w = e % HW;
            sdx[L - 1 - (w * HW + h)].y = xsrc[e];
        }
    }

    // ---- phase 0b: delta = softplus(dts . w + b) ----
    float wr[6];
    #pragma unroll
    for (int r = 0; r < 6; r++) wr[r] = dtw[kd * 6 + r];
    const float b = dtb[kd];
    const float* __restrict__ dbase = g_dts + K * RR * L;
    for (int e = tid; e < L; e += 256) {
        float a = b;
        #pragma unroll
        for (int r = 0; r < 6; r++) a = fmaf(dbase[r * L + e], wr[r], a);
        sdx[e].x = softplusf(a);
    }
    __syncthreads();

    // ---- phase A: per-chunk scan ----
    const int g = tid >> 2, n4 = tid & 3;
    float4 al = *(const float4*)&alogs[kd * NS + n4 * 4];
    const float a20 = -__expf(al.x) * LOG2E;
    const float a21 = -__expf(al.y) * LOG2E;
    const float a22 = -__expf(al.z) * LOG2E;
    const float a23 = -__expf(al.w) * LOG2E;
    const float* __restrict__ bbase = g_Bs + K * L * NS + n4 * 4;
    const int l0 = g * CL;

    float h0 = 0.f, h1 = 0.f, h2 = 0.f, h3 = 0.f, sd = 0.f;
    {
        int l = l0;
        int m = g * NS;                  // (i*64+g)*16, i=0
        #pragma unroll 7
        for (int i = 0; i < CL; i++, l++, m += NCH * NS) {
            float2 dx = sdx[l];
            float4 Bv = *(const float4*)&bbase[m];
            float dxv = dx.x * dx.y;
            h0 = fmaf(ex2f(dx.x * a20), h0, dxv * Bv.x);
            h1 = fmaf(ex2f(dx.x * a21), h1, dxv * Bv.y);
            h2 = fmaf(ex2f(dx.x * a22), h2, dxv * Bv.z);
            h3 = fmaf(ex2f(dx.x * a23), h3, dxv * Bv.w);
            sd += dx.x;
        }
    }
    float4 P, H;
    P.x = ex2f(a20 * sd); P.y = ex2f(a21 * sd);
    P.z = ex2f(a22 * sd); P.w = ex2f(a23 * sd);
    H.x = h0; H.y = h1; H.z = h2; H.w = h3;
    *(float4*)&sP[tid * 4] = P;
    *(float4*)&sH[tid * 4] = H;
    __syncthreads();

    // ---- phase B: Kogge-Stone inclusive scan over 64 chunks ----
    #pragma unroll
    for (int off = 1; off < NCH; off <<= 1) {
        float4 Pp, Hp;
        const bool valid = (g >= off);
        if (valid) {
            Pp = *(const float4*)&sP[(tid - off * 4) * 4];
            Hp = *(const float4*)&sH[(tid - off * 4) * 4];
        }
        __syncthreads();
        if (valid) {
            H.x = fmaf(P.x, Hp.x, H.x); P.x *= Pp.x;
            H.y = fmaf(P.y, Hp.y, H.y); P.y *= Pp.y;
            H.z = fmaf(P.z, Hp.z, H.z); P.z *= Pp.z;
            H.w = fmaf(P.w, Hp.w, H.w); P.w *= Pp.w;
            *(float4*)&sP[tid * 4] = P;
            *(float4*)&sH[tid * 4] = H;
        }
        __syncthreads();
    }

    float4 Hin = {0.f, 0.f, 0.f, 0.f};
    if (g > 0) Hin = *(const float4*)&sH[(tid - 4) * 4];

    // ---- phase C: replay chunk with h_in, write y to smem ----
    const float Dv = ds[kd];
    const float* __restrict__ cbase = g_Cs + K * L * NS + n4 * 4;
    h0 = Hin.x; h1 = Hin.y; h2 = Hin.z; h3 = Hin.w;

    {
        int l = l0;
        int m = g * NS;
        #pragma unroll 7
        for (int i = 0; i < CL; i++, l++, m += NCH * NS) {
            float2 dx = sdx[l];
            float4 Bv = *(const float4*)&bbase[m];
            float4 Cv = *(const float4*)&cbase[m];
            float dxv = dx.x * dx.y;
            h0 = fmaf(ex2f(dx.x * a20), h0, dxv * Bv.x);
            h1 = fmaf(ex2f(dx.x * a21), h1, dxv * Bv.y);
            h2 = fmaf(ex2f(dx.x * a22), h2, dxv * Bv.z);
            h3 = fmaf(ex2f(dx.x * a23), h3, dxv * Bv.w);
            float v = h0 * Cv.x + h1 * Cv.y + h2 * Cv.z + h3 * Cv.w;
            v += __shfl_xor_sync(0xffffffffu, v, 1);
            v += __shfl_xor_sync(0xffffffffu, v, 2);
            if (n4 == 0) sy[l] = fmaf(Dv, dx.y, v);
        }
    }
    __syncthreads();

    // ---- epilogue: write y coalesced at spatial index ----
    float* __restrict__ yptr = g_y4 + kd * L;
    if (K == 0) {
        for (int e = tid; e < L; e += 256) yptr[e] = sy[e];
    } else if (K == 2) {
        for (int e = tid; e < L; e += 256) yptr[e] = sy[L - 1 - e];
    } else if (K == 1) {
        for (int e = tid; e < L; e += 256) {
            int h = e / HW, w = e % HW;
            yptr[e] = sy[w * HW + h];
        }
    } else {
        for (int e = tid; e < L; e += 256) {
            int m = L - 1 - e;
            int h = m / HW, w = m % HW;
            yptr[e] = sy[w * HW + h];
        }
    }
}

__global__ void __launch_bounds__(256) k_scan(
        const float* __restrict__ alogs, const float* __restrict__ ds,
        const float* __restrict__ dtw, const float* __restrict__ dtb) {
    __shared__ float2 sdx[L];
    __shared__ float sy[L];
    __shared__ float sP[NCH * NS];
    __shared__ float sH[NCH * NS];
    const int kd = blockIdx.x;
    const int k = kd / DI, d = kd % DI;
    switch (k) {
        case 0: scan_body<0>(kd, d, alogs, ds, dtw, dtb, sdx, sy, sP, sH); break;
        case 1: scan_body<1>(kd, d, alogs, ds, dtw, dtb, sdx, sy, sP, sH); break;
        case 2: scan_body<2>(kd, d, alogs, ds, dtw, dtb, sdx, sy, sP, sH); break;
        default: scan_body<3>(kd, d, alogs, ds, dtw, dtb, sdx, sy, sP, sH); break;
    }
}

// ---------------- K5: merge 4 dirs + LayerNorm + z-gate + out_proj --------
__global__ void k_merge_out(const float* __restrict__ lnw, const float* __restrict__ lnb,
                            const float* __restrict__ ow, float* __restrict__ out) {
    __shared__ float yt[DI * 33];
    __shared__ float red1[256], red2[256];
    __shared__ float mu_s[32], rs_s[32];
    const int s0 = blockIdx.x * 32;
    const int tid = threadIdx.x;

    for (int e = tid; e < DI * 32; e += 256) {
        int d = e >> 5, ls = e & 31;
        int s = s0 + ls;
        float v = g_y4[d * L + s] + g_y4[(DI + d) * L + s] +
                  g_y4[(2 * DI + d) * L + s] + g_y4[(3 * DI + d) * L + s];
        yt[d * 33 + ls] = v;
    }
    __syncthreads();
    {
        int j = tid >> 5, ls = tid & 31;
        float s1 = 0.f, s2 = 0.f;
        for (int d = j; d < DI; d += 8) {
            float v = yt[d * 33 + ls];
            s1 += v; s2 += v * v;
        }
        red1[tid] = s1; red2[tid] = s2;
    }
    __syncthreads();
    if (tid < 32) {
        float s1 = 0.f, s2 = 0.f;
        #pragma unroll
        for (int j = 0; j < 8; j++) { s1 += red1[j * 32 + tid]; s2 += red2[j * 32 + tid]; }
        float mu = s1 / DI;
        float var = s2 / DI - mu * mu;
        mu_s[tid] = mu;
        rs_s[tid] = rsqrtf(var + 1e-5f);
    }
    __syncthreads();
    for (int e = tid; e < DI * 32; e += 256) {
        int ls = e / DI, d = e % DI;
        float v = yt[d * 33 + ls];
        v = (v - mu_s[ls]) * rs_s[ls] * lnw[d] + lnb[d];
        v *= g_z[(s0 + ls) * DI + d];
        yt[d * 33 + ls] = v;
    }
    __syncthreads();
    {
        int ls = tid & 31, og = tid >> 5;
        float acc[12] = {};
        for (int d = 0; d < DI; d++) {
            float yv = yt[d * 33 + ls];
            #pragma unroll
            for (int j = 0; j < 12; j++) acc[j] += yv * __ldg(&ow[(og + 8 * j) * DI + d]);
        }
        #pragma unroll
        for (int j = 0; j < 12; j++) out[(s0 + ls) * DM + og + 8 * j] = acc[j];
    }
}

// ---------------- launch ---------------------------------------------------
extern "C" void kernel_launch(void* const* d_in, const int* in_sizes, int n_in,
                              void* d_out, int out_size) {
    const float* x     = (const float*)d_in[0];
    const float* inw   = (const float*)d_in[1];
    const float* cw    = (const float*)d_in[2];
    const float* cb    = (const float*)d_in[3];
    const float* xpw   = (const float*)d_in[4];
    const float* dtw   = (const float*)d_in[5];
    const float* dtb   = (const float*)d_in[6];
    const float* alogs = (const float*)d_in[7];
    const float* ds    = (const float*)d_in[8];
    const float* lnw   = (const float*)d_in[9];
    const float* lnb   = (const float*)d_in[10];
    const float* ow    = (const float*)d_in[11];
    float* out = (float*)d_out;

    k_inproj<<<dim3(98, 6), 256>>>(x, inw);
    k_conv<<<dim3(192, 14), dim3(56, 4)>>>(cw, cb);
    k_xdbl<<<dim3(98, 4), 256>>>(xpw);
    k_scan<<<768, 256>>>(alogs, ds, dtw, dtb);
    k_merge_out<<<98, 256>>>(lnw, lnb, ow, out);
}

// round 11
// speedup vs baseline: 7.5495x; 1.0027x over previous
#include <cuda_runtime.h>
#include <math.h>

#define L    3136
#define HW   56
#define DM   96
#define DI   192
#define NS   16
#define KDIR 4
#define RR   6
#define NCH  64
#define CL   49
#define SYPAD (HW * 57)   // 3192: padded 56x57 transpose buffer

// ---------------- scratch (device globals; no allocation) ----------------
__device__ float g_xc[DI * L];           // conv input, channel-major [d][s]
__device__ float g_z[L * DI];            // gate, pixel-major [s][d]
__device__ float g_xconv[DI * L];        // conv output, channel-major [d][s]
__device__ float g_dts[KDIR * RR * L];   // low-rank dt, scan order [k*6+r][l]
// B/C in CHUNK-INTERLEAVED scan order: index (i*64+c)*16+n where l = c*49+i
__device__ float g_Bs[KDIR * L * NS];
__device__ float g_Cs[KDIR * L * NS];
__device__ float g_y4[KDIR * DI * L];    // per-direction y at SPATIAL index

__device__ __forceinline__ float siluf(float x) { return x / (1.f + __expf(-x)); }
__device__ __forceinline__ float softplusf(float x) {
    return x > 20.f ? x : __logf(1.f + __expf(x));
}
__device__ __forceinline__ float ex2f(float x) {
    float r;
    asm("ex2.approx.f32 %0, %1;" : "=f"(r) : "f"(x));
    return r;
}
#define LOG2E 1.4426950408889634f

// ---------------- K1: in_proj GEMM (L x 96) @ (96 x 384), split xc/z ------
__global__ void k_inproj(const float* __restrict__ x, const float* __restrict__ w) {
    __shared__ float As[32 * 96];
    __shared__ float Bs[96 * 65];
    __shared__ float Csh[64 * 33];
    const int l0 = blockIdx.x * 32;
    const int o0 = blockIdx.y * 64;
    const int tid = threadIdx.x;

    for (int e = tid; e < 32 * 96; e += 256)
        As[e] = x[(l0 + e / 96) * 96 + (e % 96)];
    for (int e = tid; e < 96 * 64; e += 256) {
        int o = e / 96, c = e % 96;
        Bs[c * 65 + o] = w[(o0 + o) * 96 + c];
    }
    __syncthreads();

    const int tl = tid >> 5, to = tid & 31;
    float acc[4][2] = {};
    #pragma unroll 8
    for (int kk = 0; kk < 96; kk++) {
        float b0 = Bs[kk * 65 + to];
        float b1 = Bs[kk * 65 + to + 32];
        #pragma unroll
        for (int i = 0; i < 4; i++) {
            float a = As[(tl * 4 + i) * 96 + kk];
            acc[i][0] += a * b0;
            acc[i][1] += a * b1;
        }
    }
    __syncthreads();
    #pragma unroll
    for (int i = 0; i < 4; i++) {
        Csh[to * 33 + tl * 4 + i] = acc[i][0];
        Csh[(to + 32) * 33 + tl * 4 + i] = acc[i][1];
    }
    __syncthreads();

    for (int e = tid; e < 2048; e += 256) {
        int ol = e >> 5, l = e & 31;
        int o = o0 + ol;
        if (o < DI) g_xc[o * L + l0 + l] = Csh[ol * 33 + l];
    }
    for (int e = tid; e < 2048; e += 256) {
        int l = e >> 6, ol = e & 63;
        int o = o0 + ol;
        if (o >= DI) {
            float v = Csh[ol * 33 + l];
            g_z[(l0 + l) * DI + (o - DI)] = siluf(v);
        }
    }
}

// ---------------- K2: depthwise 3x3 conv SAME + silu ----------------------
__global__ void k_conv(const float* __restrict__ cw, const float* __restrict__ cb) {
    const int d = blockIdx.x;
    const int h = blockIdx.y * 4 + threadIdx.y;
    const int w = threadIdx.x;
    float wgt[9];
    #pragma unroll
    for (int i = 0; i < 9; i++) wgt[i] = cw[d * 9 + i];
    float acc = cb[d];
    const float* base = g_xc + d * L;
    #pragma unroll
    for (int i = 0; i < 3; i++) {
        int hh = h + i - 1;
        if (hh < 0 || hh >= HW) continue;
        #pragma unroll
        for (int j = 0; j < 3; j++) {
            int ww = w + j - 1;
            if (ww < 0 || ww >= HW) continue;
            acc += base[hh * HW + ww] * wgt[i * 3 + j];
        }
    }
    g_xconv[d * L + h * HW + w] = siluf(acc);
}

// ---------------- K3: x_dbl projection GEMM, scatter into scan order -----
#define XD_KC 96
__global__ void k_xdbl(const float* __restrict__ xpw) {
    __shared__ float ws[40 * XD_KC];    // [row][dd]
    __shared__ float xs[XD_KC * 32];    // [dd][ss]
    const int k = blockIdx.y;
    const int s0 = blockIdx.x * 32;
    const int tid = threadIdx.x;
    const int tx = tid & 31;
    const int ty = tid >> 5;
    const int r0 = ty * 5;

    float acc[5] = {};

    for (int d0 = 0; d0 < DI; d0 += XD_KC) {
        __syncthreads();
        for (int e = tid; e < 40 * XD_KC; e += 256) {
            int row = e / XD_KC, dd = e % XD_KC;
            ws[e] = (row < 38) ? xpw[(k * 38 + row) * DI + d0 + dd] : 0.f;
        }
        #pragma unroll
        for (int e = tid; e < XD_KC * 32; e += 256) {
            int dd = e >> 5, ss = e & 31;
            xs[e] = g_xconv[(d0 + dd) * L + s0 + ss];
        }
        __syncthreads();
        #pragma unroll 8
        for (int dd = 0; dd < XD_KC; dd++) {
            float xv = xs[dd * 32 + tx];
            #pragma unroll
            for (int j = 0; j < 5; j++)
                acc[j] = fmaf(ws[(r0 + j) * XD_KC + dd], xv, acc[j]);
        }
    }

    #pragma unroll
    for (int j = 0; j < 5; j++) {
        int r = r0 + j;
        if (r >= 38) break;
        int s = s0 + tx;
        int hs = s / HW, wsp = s % HW;
        int tpos = wsp * HW + hs;
        int lp = (k == 0) ? s : (k == 1) ? tpos : (k == 2) ? (L - 1 - s) : (L - 1 - tpos);
        float v = acc[j];
        if (r < RR) {
            g_dts[(k * RR + r) * L + lp] = v;
        } else {
            int cc = lp / CL, ii = lp - cc * CL;
            int pos = k * L * NS + (ii * NCH + cc) * NS;
            if (r < RR + NS) g_Bs[pos + (r - RR)] = v;
            else             g_Cs[pos + (r - RR - NS)] = v;
        }
    }
}

// ---------------- K4: fused scan -------------------------------------------
// One block per kd. 256 threads = 64 groups x 4 lanes, chunk = 49 steps.
// smem: sdx[L] float2, sy[SYPAD] float (hosts pad-staging and aliased sP/sH).
template<int K>
__device__ __forceinline__ void scan_body(
    int kd, int d,
    const float* __restrict__ alogs, const float* __restrict__ ds,
    const float* __restrict__ dtw, const float* __restrict__ dtb,
    float2* __restrict__ sdx, float* __restrict__ sy)
{
    const int tid = threadIdx.x;
    float* __restrict__ sP = sy;          // aliased: [0..1023]
    float* __restrict__ sH = sy + 1024;   // aliased: [1024..2047]

    // ---- phase 0a (K=1/3 only): stage x into padded 56x57 buffer in sy ----
    const float* __restrict__ xsrc = g_xconv + d * L;
    if (K == 1 || K == 3) {
        for (int e = tid; e < L; e += 256)
            sy[(e / HW) * 57 + (e % HW)] = xsrc[e];
        __syncthreads();
    }

    // ---- phase 0b: sdx[e] = (delta, x) in scan order ----
    float wr[6];
    #pragma unroll
    for (int r = 0; r < 6; r++) wr[r] = dtw[kd * 6 + r];
    const float b = dtb[kd];
    const float* __restrict__ dbase = g_dts + K * RR * L;
    for (int e = tid; e < L; e += 256) {
        float a = b;
        #pragma unroll
        for (int r = 0; r < 6; r++) a = fmaf(dbase[r * L + e], wr[r], a);
        float xv;
        if (K == 0) xv = xsrc[e];
        else if (K == 2) xv = xsrc[L - 1 - e];
        else {
            int m = (K == 1) ? e : (L - 1 - e);
            xv = sy[(m % HW) * 57 + (m / HW)];
        }
        float2 o; o.x = softplusf(a); o.y = xv;
        sdx[e] = o;
    }
    __syncthreads();

    // ---- setup per-lane state constants + fast-path detection ----
    const int g = tid >> 2, n4 = tid & 3;
    float4 al = *(const float4*)&alogs[kd * NS + n4 * 4];
    const float a20 = -__expf(al.x) * LOG2E;
    const float a21 = -__expf(al.y) * LOG2E;
    const float a22 = -__expf(al.z) * LOG2E;
    const float a23 = -__expf(al.w) * LOG2E;
    bool fp = (al.x == al.y) && (al.x == al.z) && (al.x == al.w) &&
              (al.x == __shfl_sync(0xffffffffu, al.x, 0));
    fp = __all_sync(0xffffffffu, fp);

    const float* __restrict__ bbase = g_Bs + K * L * NS + n4 * 4;
    const int l0 = g * CL;

    // ---- phase A: per-chunk scan ----
    float h0 = 0.f, h1 = 0.f, h2 = 0.f, h3 = 0.f, sd = 0.f;
    if (fp) {
        int l = l0, m = g * NS;
        #pragma unroll 7
        for (int i = 0; i < CL; i++, l++, m += NCH * NS) {
            float2 dx = sdx[l];
            float4 Bv = *(const float4*)&bbase[m];
            float dxv = dx.x * dx.y;
            float dA = ex2f(dx.x * a20);
            h0 = fmaf(dA, h0, dxv * Bv.x);
            h1 = fmaf(dA, h1, dxv * Bv.y);
            h2 = fmaf(dA, h2, dxv * Bv.z);
            h3 = fmaf(dA, h3, dxv * Bv.w);
            sd += dx.x;
        }
    } else {
        int l = l0, m = g * NS;
        #pragma unroll 7
        for (int i = 0; i < CL; i++, l++, m += NCH * NS) {
            float2 dx = sdx[l];
            float4 Bv = *(const float4*)&bbase[m];
            float dxv = dx.x * dx.y;
            h0 = fmaf(ex2f(dx.x * a20), h0, dxv * Bv.x);
            h1 = fmaf(ex2f(dx.x * a21), h1, dxv * Bv.y);
            h2 = fmaf(ex2f(dx.x * a22), h2, dxv * Bv.z);
            h3 = fmaf(ex2f(dx.x * a23), h3, dxv * Bv.w);
            sd += dx.x;
        }
    }
    float4 P, H;
    if (fp) { P.x = ex2f(a20 * sd); P.y = P.x; P.z = P.x; P.w = P.x; }
    else {
        P.x = ex2f(a20 * sd); P.y = ex2f(a21 * sd);
        P.z = ex2f(a22 * sd); P.w = ex2f(a23 * sd);
    }
    H.x = h0; H.y = h1; H.z = h2; H.w = h3;
    __syncthreads();   // K=1/3: staging reads in phase 0b done before aliasing
    *(float4*)&sP[tid * 4] = P;
    *(float4*)&sH[tid * 4] = H;
    __syncthreads();

    // ---- phase B: Kogge-Stone inclusive scan over 64 chunks ----
    #pragma unroll
    for (int off = 1; off < NCH; off <<= 1) {
        float4 Pp, Hp;
        const bool valid = (g >= off);
        if (valid) {
            Pp = *(const float4*)&sP[(tid - off * 4) * 4];
            Hp = *(const float4*)&sH[(tid - off * 4) * 4];
        }
        __syncthreads();
        if (valid) {
            H.x = fmaf(P.x, Hp.x, H.x); P.x *= Pp.x;
            H.y = fmaf(P.y, Hp.y, H.y); P.y *= Pp.y;
            H.z = fmaf(P.z, Hp.z, H.z); P.z *= Pp.z;
            H.w = fmaf(P.w, Hp.w, H.w); P.w *= Pp.w;
            *(float4*)&sP[tid * 4] = P;
            *(float4*)&sH[tid * 4] = H;
        }
        __syncthreads();
    }

    float4 Hin = {0.f, 0.f, 0.f, 0.f};
    if (g > 0) Hin = *(const float4*)&sH[(tid - 4) * 4];
    __syncthreads();   // all Hin reads done before sy (=sP/sH) is overwritten

    // ---- phase C: replay chunk with h_in, write y to smem ----
    const float Dv = ds[kd];
    const float* __restrict__ cbase = g_Cs + K * L * NS + n4 * 4;
    h0 = Hin.x; h1 = Hin.y; h2 = Hin.z; h3 = Hin.w;

    if (fp) {
        int l = l0, m = g * NS;
        #pragma unroll 7
        for (int i = 0; i < CL; i++, l++, m += NCH * NS) {
            float2 dx = sdx[l];
            float4 Bv = *(const float4*)&bbase[m];
            float4 Cv = *(const float4*)&cbase[m];
            float dxv = dx.x * dx.y;
            float dA = ex2f(dx.x * a20);
            h0 = fmaf(dA, h0, dxv * Bv.x);
            h1 = fmaf(dA, h1, dxv * Bv.y);
            h2 = fmaf(dA, h2, dxv * Bv.z);
            h3 = fmaf(dA, h3, dxv * Bv.w);
            float v = h0 * Cv.x + h1 * Cv.y + h2 * Cv.z + h3 * Cv.w;
            v += __shfl_xor_sync(0xffffffffu, v, 1);
            v += __shfl_xor_sync(0xffffffffu, v, 2);
            if (n4 == 0) sy[l] = fmaf(Dv, dx.y, v);
        }
    } else {
        int l = l0, m = g * NS;
        #pragma unroll 7
        for (int i = 0; i < CL; i++, l++, m += NCH * NS) {
            float2 dx = sdx[l];
            float4 Bv = *(const float4*)&bbase[m];
            float4 Cv = *(const float4*)&cbase[m];
            float dxv = dx.x * dx.y;
            h0 = fmaf(ex2f(dx.x * a20), h0, dxv * Bv.x);
            h1 = fmaf(ex2f(dx.x * a21), h1, dxv * Bv.y);
            h2 = fmaf(ex2f(dx.x * a22), h2, dxv * Bv.z);
            h3 = fmaf(ex2f(dx.x * a23), h3, dxv * Bv.w);
            float v = h0 * Cv.x + h1 * Cv.y + h2 * Cv.z + h3 * Cv.w;
            v += __shfl_xor_sync(0xffffffffu, v, 1);
            v += __shfl_xor_sync(0xffffffffu, v, 2);
            if (n4 == 0) sy[l] = fmaf(Dv, dx.y, v);
        }
    }
    __syncthreads();

    // ---- epilogue: write y coalesced at spatial index ----
    float* __restrict__ yptr = g_y4 + kd * L;
    if (K == 0) {
        for (int e = tid; e < L; e += 256) yptr[e] = sy[e];
    } else if (K == 2) {
        for (int e = tid; e < L; e += 256) yptr[e] = sy[L - 1 - e];
    } else {
        // stage via padded buffer in (dead) sdx region to avoid bank conflicts
        float* __restrict__ tmp = (float*)sdx;
        for (int l = tid; l < L; l += 256) {
            int m = (K == 1) ? l : (L - 1 - l);
            tmp[(m / HW) * 57 + (m % HW)] = sy[l];
        }
        __syncthreads();
        for (int e = tid; e < L; e += 256) {
            int h = e / HW, w = e % HW;
            yptr[e] = tmp[w * 57 + h];
        }
    }
}

__global__ void __launch_bounds__(256, 5) k_scan(
        const float* __restrict__ alogs, const float* __restrict__ ds,
        const float* __restrict__ dtw, const float* __restrict__ dtb) {
    __shared__ float2 sdx[L];
    __shared__ float sy[SYPAD];
    const int kd = blockIdx.x;
    const int k = kd / DI, d = kd % DI;
    switch (k) {
        case 0: scan_body<0>(kd, d, alogs, ds, dtw, dtb, sdx, sy); break;
        case 1: scan_body<1>(kd, d, alogs, ds, dtw, dtb, sdx, sy); break;
        case 2: scan_body<2>(kd, d, alogs, ds, dtw, dtb, sdx, sy); break;
        default: scan_body<3>(kd, d, alogs, ds, dtw, dtb, sdx, sy); break;
    }
}

// ---------------- K5: merge 4 dirs + LayerNorm + z-gate + out_proj --------
__global__ void k_merge_out(const float* __restrict__ lnw, const float* __restrict__ lnb,
                            const float* __restrict__ ow, float* __restrict__ out) {
    __shared__ float yt[DI * 33];
    __shared__ float red1[256], red2[256];
    __shared__ float mu_s[32], rs_s[32];
    const int s0 = blockIdx.x * 32;
    const int tid = threadIdx.x;

    for (int e = tid; e < DI * 32; e += 256) {
        int d = e >> 5, ls = e & 31;
        int s = s0 + ls;
        float v = g_y4[d * L + s] + g_y4[(DI + d) * L + s] +
                  g_y4[(2 * DI + d) * L + s] + g_y4[(3 * DI + d) * L + s];
        yt[d * 33 + ls] = v;
    }
    __syncthreads();
    {
        int j = tid >> 5, ls = tid & 31;
        float s1 = 0.f, s2 = 0.f;
        for (int d = j; d < DI; d += 8) {
            float v = yt[d * 33 + ls];
            s1 += v; s2 += v * v;
        }
        red1[tid] = s1; red2[tid] = s2;
    }
    __syncthreads();
    if (tid < 32) {
        float s1 = 0.f, s2 = 0.f;
        #pragma unroll
        for (int j = 0; j < 8; j++) { s1 += red1[j * 32 + tid]; s2 += red2[j * 32 + tid]; }
        float mu = s1 / DI;
        float var = s2 / DI - mu * mu;
        mu_s[tid] = mu;
        rs_s[tid] = rsqrtf(var + 1e-5f);
    }
    __syncthreads();
    for (int e = tid; e < DI * 32; e += 256) {
        int ls = e / DI, d = e % DI;
        float v = yt[d * 33 + ls];
        v = (v - mu_s[ls]) * rs_s[ls] * lnw[d] + lnb[d];
        v *= g_z[(s0 + ls) * DI + d];
        yt[d * 33 + ls] = v;
    }
    __syncthreads();
    {
        int ls = tid & 31, og = tid >> 5;
        float acc[12] = {};
        for (int d = 0; d < DI; d++) {
            float yv = yt[d * 33 + ls];
            #pragma unroll
            for (int j = 0; j < 12; j++) acc[j] += yv * __ldg(&ow[(og + 8 * j) * DI + d]);
        }
        #pragma unroll
        for (int j = 0; j < 12; j++) out[(s0 + ls) * DM + og + 8 * j] = acc[j];
    }
}

// ---------------- launch ---------------------------------------------------
extern "C" void kernel_launch(void* const* d_in, const int* in_sizes, int n_in,
                              void* d_out, int out_size) {
    const float* x     = (const float*)d_in[0];
    const float* inw   = (const float*)d_in[1];
    const float* cw    = (const float*)d_in[2];
    const float* cb    = (const float*)d_in[3];
    const float* xpw   = (const float*)d_in[4];
    const float* dtw   = (const float*)d_in[5];
    const float* dtb   = (const float*)d_in[6];
    const float* alogs = (const float*)d_in[7];
    const float* ds    = (const float*)d_in[8];
    const float* lnw   = (const float*)d_in[9];
    const float* lnb   = (const float*)d_in[10];
    const float* ow    = (const float*)d_in[11];
    float* out = (float*)d_out;

    k_inproj<<<dim3(98, 6), 256>>>(x, inw);
    k_conv<<<dim3(192, 14), dim3(56, 4)>>>(cw, cb);
    k_xdbl<<<dim3(98, 4), 256>>>(xpw);
    k_scan<<<768, 256>>>(alogs, ds, dtw, dtb);
    k_merge_out<<<98, 256>>>(lnw, lnb, ow, out);
}

// round 12
// speedup vs baseline: 7.6282x; 1.0104x over previous
#include <cuda_runtime.h>
#include <math.h>

#define L    3136
#define HW   56
#define DM   96
#define DI   192
#define NS   16
#define KDIR 4
#define RR   6
#define NCH  64
#define CL   49

// ---------------- scratch (device globals; no allocation) ----------------
__device__ float g_xc[DI * L];           // conv input, channel-major [d][s]
__device__ float g_z[L * DI];            // gate, pixel-major [s][d]
__device__ float g_xconv[DI * L];        // conv output, channel-major [d][s]
__device__ float g_xt[DI * L];           // transposed: xt[d][j] = xconv[d][(j%56)*56+j/56]
__device__ float g_dts[KDIR * RR * L];   // low-rank dt, scan order [k*6+r][l]
// B/C in CHUNK-INTERLEAVED scan order: index (i*64+c)*16+n where l = c*49+i
__device__ float g_Bs[KDIR * L * NS];
__device__ float g_Cs[KDIR * L * NS];
__device__ float g_y4[KDIR * DI * L];    // per-direction y at SPATIAL index

__device__ __forceinline__ float siluf(float x) { return x / (1.f + __expf(-x)); }
__device__ __forceinline__ float softplusf(float x) {
    return x > 20.f ? x : __logf(1.f + __expf(x));
}
__device__ __forceinline__ float ex2f(float x) {
    float r;
    asm("ex2.approx.f32 %0, %1;" : "=f"(r) : "f"(x));
    return r;
}
#define LOG2E 1.4426950408889634f

// ---------------- K1: in_proj GEMM (L x 96) @ (96 x 384), split xc/z ------
__global__ void k_inproj(const float* __restrict__ x, const float* __restrict__ w) {
    __shared__ float As[32 * 96];
    __shared__ float Bs[96 * 65];
    __shared__ float Csh[64 * 33];
    const int l0 = blockIdx.x * 32;
    const int o0 = blockIdx.y * 64;
    const int tid = threadIdx.x;

    for (int e = tid; e < 32 * 96; e += 256)
        As[e] = x[(l0 + e / 96) * 96 + (e % 96)];
    for (int e = tid; e < 96 * 64; e += 256) {
        int o = e / 96, c = e % 96;
        Bs[c * 65 + o] = w[(o0 + o) * 96 + c];
    }
    __syncthreads();

    const int tl = tid >> 5, to = tid & 31;
    float acc[4][2] = {};
    #pragma unroll 8
    for (int kk = 0; kk < 96; kk++) {
        float b0 = Bs[kk * 65 + to];
        float b1 = Bs[kk * 65 + to + 32];
        #pragma unroll
        for (int i = 0; i < 4; i++) {
            float a = As[(tl * 4 + i) * 96 + kk];
            acc[i][0] += a * b0;
            acc[i][1] += a * b1;
        }
    }
    __syncthreads();
    #pragma unroll
    for (int i = 0; i < 4; i++) {
        Csh[to * 33 + tl * 4 + i] = acc[i][0];
        Csh[(to + 32) * 33 + tl * 4 + i] = acc[i][1];
    }
    __syncthreads();

    for (int e = tid; e < 2048; e += 256) {
        int ol = e >> 5, l = e & 31;
        int o = o0 + ol;
        if (o < DI) g_xc[o * L + l0 + l] = Csh[ol * 33 + l];
    }
    for (int e = tid; e < 2048; e += 256) {
        int l = e >> 6, ol = e & 63;
        int o = o0 + ol;
        if (o >= DI) {
            float v = Csh[ol * 33 + l];
            g_z[(l0 + l) * DI + (o - DI)] = siluf(v);
        }
    }
}

// ---------------- K2: depthwise 3x3 conv SAME + silu ----------------------
__global__ void k_conv(const float* __restrict__ cw, const float* __restrict__ cb) {
    const int d = blockIdx.x;
    const int h = blockIdx.y * 4 + threadIdx.y;
    const int w = threadIdx.x;
    float wgt[9];
    #pragma unroll
    for (int i = 0; i < 9; i++) wgt[i] = cw[d * 9 + i];
    float acc = cb[d];
    const float* base = g_xc + d * L;
    #pragma unroll
    for (int i = 0; i < 3; i++) {
        int hh = h + i - 1;
        if (hh < 0 || hh >= HW) continue;
        #pragma unroll
        for (int j = 0; j < 3; j++) {
            int ww = w + j - 1;
            if (ww < 0 || ww >= HW) continue;
            acc += base[hh * HW + ww] * wgt[i * 3 + j];
        }
    }
    g_xconv[d * L + h * HW + w] = siluf(acc);
}

// ---------------- K2b: transpose xconv -> g_xt -----------------------------
__global__ void k_xt() {
    __shared__ float t[56][57];
    const int d = blockIdx.x;
    const int tid = threadIdx.x;
    const float* src = g_xconv + d * L;
    float* dst = g_xt + d * L;
    for (int e = tid; e < L; e += 256) t[e / 56][e % 56] = src[e];
    __syncthreads();
    for (int e = tid; e < L; e += 256) dst[e] = t[e % 56][e / 56];
}

// ---------------- K3: x_dbl projection GEMM, scatter into scan order -----
#define XD_KC 96
__global__ void k_xdbl(const float* __restrict__ xpw) {
    __shared__ float ws[40 * XD_KC];    // [row][dd]
    __shared__ float xs[XD_KC * 32];    // [dd][ss]
    const int k = blockIdx.y;
    const int s0 = blockIdx.x * 32;
    const int tid = threadIdx.x;
    const int tx = tid & 31;
    const int ty = tid >> 5;
    const int r0 = ty * 5;

    float acc[5] = {};

    for (int d0 = 0; d0 < DI; d0 += XD_KC) {
        __syncthreads();
        for (int e = tid; e < 40 * XD_KC; e += 256) {
            int row = e / XD_KC, dd = e % XD_KC;
            ws[e] = (row < 38) ? xpw[(k * 38 + row) * DI + d0 + dd] : 0.f;
        }
        #pragma unroll
        for (int e = tid; e < XD_KC * 32; e += 256) {
            int dd = e >> 5, ss = e & 31;
            xs[e] = g_xconv[(d0 + dd) * L + s0 + ss];
        }
        __syncthreads();
        #pragma unroll 8
        for (int dd = 0; dd < XD_KC; dd++) {
            float xv = xs[dd * 32 + tx];
            #pragma unroll
            for (int j = 0; j < 5; j++)
                acc[j] = fmaf(ws[(r0 + j) * XD_KC + dd], xv, acc[j]);
        }
    }

    #pragma unroll
    for (int j = 0; j < 5; j++) {
        int r = r0 + j;
        if (r >= 38) break;
        int s = s0 + tx;
        int hs = s / HW, wsp = s % HW;
        int tpos = wsp * HW + hs;
        int lp = (k == 0) ? s : (k == 1) ? tpos : (k == 2) ? (L - 1 - s) : (L - 1 - tpos);
        float v = acc[j];
        if (r < RR) {
            g_dts[(k * RR + r) * L + lp] = v;
        } else {
            int cc = lp / CL, ii = lp - cc * CL;
            int pos = k * L * NS + (ii * NCH + cc) * NS;
            if (r < RR + NS) g_Bs[pos + (r - RR)] = v;
            else             g_Cs[pos + (r - RR - NS)] = v;
        }
    }
}

// ---------------- K4: fused scan -------------------------------------------
// One block per kd. 256 threads = 64 groups x 4 lanes, chunk = 49 steps.
// smem: sdx[L] float2 (y written back into .x in phase C), sps[2048] (sP/sH,
// later 28x57 transpose tiles for the K=1/3 epilogue).
template<int K>
__device__ __forceinline__ void scan_body(
    int kd, int d,
    const float* __restrict__ alogs, const float* __restrict__ ds,
    const float* __restrict__ dtw, const float* __restrict__ dtb,
    float2* __restrict__ sdx, float* __restrict__ sps)
{
    const int tid = threadIdx.x;
    float* __restrict__ sP = sps;          // [0..1023]
    float* __restrict__ sH = sps + 1024;   // [1024..2047]

    // ---- phase 0: sdx[e] = (delta, x) in scan order (x from xconv/xt) ----
    float wr[6];
    #pragma unroll
    for (int r = 0; r < 6; r++) wr[r] = dtw[kd * 6 + r];
    const float b = dtb[kd];
    const float* __restrict__ dbase = g_dts + K * RR * L;
    const float* __restrict__ xsrc = ((K & 1) ? g_xt : g_xconv) + d * L;
    for (int e = tid; e < L; e += 256) {
        float a = b;
        #pragma unroll
        for (int r = 0; r < 6; r++) a = fmaf(dbase[r * L + e], wr[r], a);
        float xv = (K < 2) ? xsrc[e] : xsrc[L - 1 - e];
        float2 o; o.x = softplusf(a); o.y = xv;
        sdx[e] = o;
    }
    __syncthreads();

    // ---- setup per-lane state constants + fast-path detection ----
    const int g = tid >> 2, n4 = tid & 3;
    float4 al = *(const float4*)&alogs[kd * NS + n4 * 4];
    const float a20 = -__expf(al.x) * LOG2E;
    const float a21 = -__expf(al.y) * LOG2E;
    const float a22 = -__expf(al.z) * LOG2E;
    const float a23 = -__expf(al.w) * LOG2E;
    bool fp = (al.x == al.y) && (al.x == al.z) && (al.x == al.w) &&
              (al.x == __shfl_sync(0xffffffffu, al.x, 0));
    fp = __all_sync(0xffffffffu, fp);

    const float* __restrict__ bbase = g_Bs + K * L * NS + n4 * 4;
    const int l0 = g * CL;

    // ---- phase A: per-chunk scan ----
    float h0 = 0.f, h1 = 0.f, h2 = 0.f, h3 = 0.f, sd = 0.f;
    if (fp) {
        int l = l0, m = g * NS;
        #pragma unroll 7
        for (int i = 0; i < CL; i++, l++, m += NCH * NS) {
            float2 dx = sdx[l];
            float4 Bv = *(const float4*)&bbase[m];
            float dxv = dx.x * dx.y;
            float dA = ex2f(dx.x * a20);
            h0 = fmaf(dA, h0, dxv * Bv.x);
            h1 = fmaf(dA, h1, dxv * Bv.y);
            h2 = fmaf(dA, h2, dxv * Bv.z);
            h3 = fmaf(dA, h3, dxv * Bv.w);
            sd += dx.x;
        }
    } else {
        int l = l0, m = g * NS;
        #pragma unroll 7
        for (int i = 0; i < CL; i++, l++, m += NCH * NS) {
            float2 dx = sdx[l];
            float4 Bv = *(const float4*)&bbase[m];
            float dxv = dx.x * dx.y;
            h0 = fmaf(ex2f(dx.x * a20), h0, dxv * Bv.x);
            h1 = fmaf(ex2f(dx.x * a21), h1, dxv * Bv.y);
            h2 = fmaf(ex2f(dx.x * a22), h2, dxv * Bv.z);
            h3 = fmaf(ex2f(dx.x * a23), h3, dxv * Bv.w);
            sd += dx.x;
        }
    }
    float4 P, H;
    if (fp) { P.x = ex2f(a20 * sd); P.y = P.x; P.z = P.x; P.w = P.x; }
    else {
        P.x = ex2f(a20 * sd); P.y = ex2f(a21 * sd);
        P.z = ex2f(a22 * sd); P.w = ex2f(a23 * sd);
    }
    H.x = h0; H.y = h1; H.z = h2; H.w = h3;
    *(float4*)&sP[tid * 4] = P;
    *(float4*)&sH[tid * 4] = H;
    __syncthreads();

    // ---- phase B: Kogge-Stone inclusive scan over 64 chunks ----
    #pragma unroll
    for (int off = 1; off < NCH; off <<= 1) {
        float4 Pp, Hp;
        const bool valid = (g >= off);
        if (valid) {
            Pp = *(const float4*)&sP[(tid - off * 4) * 4];
            Hp = *(const float4*)&sH[(tid - off * 4) * 4];
        }
        __syncthreads();
        if (valid) {
            H.x = fmaf(P.x, Hp.x, H.x); P.x *= Pp.x;
            H.y = fmaf(P.y, Hp.y, H.y); P.y *= Pp.y;
            H.z = fmaf(P.z, Hp.z, H.z); P.z *= Pp.z;
            H.w = fmaf(P.w, Hp.w, H.w); P.w *= Pp.w;
            *(float4*)&sP[tid * 4] = P;
            *(float4*)&sH[tid * 4] = H;
        }
        __syncthreads();
    }

    float4 Hin = {0.f, 0.f, 0.f, 0.f};
    if (g > 0) Hin = *(const float4*)&sH[(tid - 4) * 4];
    __syncthreads();   // Hin reads done before sps is reused by epilogue

    // ---- phase C: replay chunk with h_in, write y into sdx[l].x ----
    const float Dv = ds[kd];
    const float* __restrict__ cbase = g_Cs + K * L * NS + n4 * 4;
    h0 = Hin.x; h1 = Hin.y; h2 = Hin.z; h3 = Hin.w;

    if (fp) {
        int l = l0, m = g * NS;
        #pragma unroll 7
        for (int i = 0; i < CL; i++, l++, m += NCH * NS) {
            float2 dx = sdx[l];
            float4 Bv = *(const float4*)&bbase[m];
            float4 Cv = *(const float4*)&cbase[m];
            float dxv = dx.x * dx.y;
            float dA = ex2f(dx.x * a20);
            h0 = fmaf(dA, h0, dxv * Bv.x);
            h1 = fmaf(dA, h1, dxv * Bv.y);
            h2 = fmaf(dA, h2, dxv * Bv.z);
            h3 = fmaf(dA, h3, dxv * Bv.w);
            float v = h0 * Cv.x + h1 * Cv.y + h2 * Cv.z + h3 * Cv.w;
            v += __shfl_xor_sync(0xffffffffu, v, 1);
            v += __shfl_xor_sync(0xffffffffu, v, 2);
            if (n4 == 0) sdx[l].x = fmaf(Dv, dx.y, v);  // same-warp read-then-write
        }
    } else {
        int l = l0, m = g * NS;
        #pragma unroll 7
        for (int i = 0; i < CL; i++, l++, m += NCH * NS) {
            float2 dx = sdx[l];
            float4 Bv = *(const float4*)&bbase[m];
            float4 Cv = *(const float4*)&cbase[m];
            float dxv = dx.x * dx.y;
            h0 = fmaf(ex2f(dx.x * a20), h0, dxv * Bv.x);
            h1 = fmaf(ex2f(dx.x * a21), h1, dxv * Bv.y);
            h2 = fmaf(ex2f(dx.x * a22), h2, dxv * Bv.z);
            h3 = fmaf(ex2f(dx.x * a23), h3, dxv * Bv.w);
            float v = h0 * Cv.x + h1 * Cv.y + h2 * Cv.z + h3 * Cv.w;
            v += __shfl_xor_sync(0xffffffffu, v, 1);
            v += __shfl_xor_sync(0xffffffffu, v, 2);
            if (n4 == 0) sdx[l].x = fmaf(Dv, dx.y, v);
        }
    }
    __syncthreads();

    // ---- epilogue: write y coalesced at spatial index ----
    float* __restrict__ yptr = g_y4 + kd * L;
    if (K == 0) {
        for (int e = tid; e < L; e += 256) yptr[e] = sdx[e].x;
    } else if (K == 2) {
        for (int e = tid; e < L; e += 256) yptr[e] = sdx[L - 1 - e].x;
    } else {
        // transpose through sps in two 56x28 tiles (conflict-free)
        for (int h0t = 0; h0t < HW; h0t += 28) {
            __syncthreads();
            for (int e2 = tid; e2 < HW * 28; e2 += 256) {
                int w = e2 / 28, hh = e2 % 28;
                int l = w * HW + h0t + hh;
                int li = (K == 1) ? l : (L - 1 - l);
                sps[hh * 57 + w] = sdx[li].x;
            }
            __syncthreads();
            for (int e2 = tid; e2 < HW * 28; e2 += 256) {
                int w = e2 % HW, hh = e2 / HW;
                yptr[(h0t + hh) * HW + w] = sps[hh * 57 + w];
            }
        }
    }
}

__global__ void __launch_bounds__(256, 6) k_scan(
        const float* __restrict__ alogs, const float* __restrict__ ds,
        const float* __restrict__ dtw, const float* __restrict__ dtb) {
    __shared__ float2 sdx[L];
    __shared__ float sps[2048];
    const int kd = blockIdx.x;
    const int k = kd / DI, d = kd % DI;
    switch (k) {
        case 0: scan_body<0>(kd, d, alogs, ds, dtw, dtb, sdx, sps); break;
        case 1: scan_body<1>(kd, d, alogs, ds, dtw, dtb, sdx, sps); break;
        case 2: scan_body<2>(kd, d, alogs, ds, dtw, dtb, sdx, sps); break;
        default: scan_body<3>(kd, d, alogs, ds, dtw, dtb, sdx, sps); break;
    }
}

// ---------------- K5: merge 4 dirs + LayerNorm + z-gate + out_proj --------
__global__ void k_merge_out(const float* __restrict__ lnw, const float* __restrict__ lnb,
                            const float* __restrict__ ow, float* __restrict__ out) {
    __shared__ float yt[DI * 33];
    __shared__ float red1[256], red2[256];
    __shared__ float mu_s[32], rs_s[32];
    const int s0 = blockIdx.x * 32;
    const int tid = threadIdx.x;

    for (int e = tid; e < DI * 32; e += 256) {
        int d = e >> 5, ls = e & 31;
        int s = s0 + ls;
        float v = g_y4[d * L + s] + g_y4[(DI + d) * L + s] +
                  g_y4[(2 * DI + d) * L + s] + g_y4[(3 * DI + d) * L + s];
        yt[d * 33 + ls] = v;
    }
    __syncthreads();
    {
        int j = tid >> 5, ls = tid & 31;
        float s1 = 0.f, s2 = 0.f;
        for (int d = j; d < DI; d += 8) {
            float v = yt[d * 33 + ls];
            s1 += v; s2 += v * v;
        }
        red1[tid] = s1; red2[tid] = s2;
    }
    __syncthreads();
    if (tid < 32) {
        float s1 = 0.f, s2 = 0.f;
        #pragma unroll
        for (int j = 0; j < 8; j++) { s1 += red1[j * 32 + tid]; s2 += red2[j * 32 + tid]; }
        float mu = s1 / DI;
        float var = s2 / DI - mu * mu;
        mu_s[tid] = mu;
        rs_s[tid] = rsqrtf(var + 1e-5f);
    }
    __syncthreads();
    for (int e = tid; e < DI * 32; e += 256) {
        int ls = e / DI, d = e % DI;
        float v = yt[d * 33 + ls];
        v = (v - mu_s[ls]) * rs_s[ls] * lnw[d] + lnb[d];
        v *= g_z[(s0 + ls) * DI + d];
        yt[d * 33 + ls] = v;
    }
    __syncthreads();
    {
        int ls = tid & 31, og = tid >> 5;
        float acc[12] = {};
        for (int d = 0; d < DI; d++) {
            float yv = yt[d * 33 + ls];
            #pragma unroll
            for (int j = 0; j < 12; j++) acc[j] += yv * __ldg(&ow[(og + 8 * j) * DI + d]);
        }
        #pragma unroll
        for (int j = 0; j < 12; j++) out[(s0 + ls) * DM + og + 8 * j] = acc[j];
    }
}

// ---------------- launch ---------------------------------------------------
extern "C" void kernel_launch(void* const* d_in, const int* in_sizes, int n_in,
                              void* d_out, int out_size) {
    const float* x     = (const float*)d_in[0];
    const float* inw   = (const float*)d_in[1];
    const float* cw    = (const float*)d_in[2];
    const float* cb    = (const float*)d_in[3];
    const float* xpw   = (const float*)d_in[4];
    const float* dtw   = (const float*)d_in[5];
    const float* dtb   = (const float*)d_in[6];
    const float* alogs = (const float*)d_in[7];
    const float* ds    = (const float*)d_in[8];
    const float* lnw   = (const float*)d_in[9];
    const float* lnb   = (const float*)d_in[10];
    const float* ow    = (const float*)d_in[11];
    float* out = (float*)d_out;

    k_inproj<<<dim3(98, 6), 256>>>(x, inw);
    k_conv<<<dim3(192, 14), dim3(56, 4)>>>(cw, cb);
    k_xt<<<192, 256>>>();
    k_xdbl<<<dim3(98, 4), 256>>>(xpw);
    k_scan<<<768, 256>>>(alogs, ds, dtw, dtb);
    k_merge_out<<<98, 256>>>(lnw, lnb, ow, out);
}